// round 1
// baseline (speedup 1.0000x reference)
#include <cuda_runtime.h>
#include <math.h>

// Problem constants
#define Bsz 8
#define SEQ 1024
#define EMB 1024
#define NH  16
#define HS  64
#define M_TOT (Bsz * SEQ)   // 8192

// Scratch: q,k,v in [B,H,S,HS]; attention out in [B,S,H,HS] (== row-major [M, E])
__device__ float g_q[Bsz * NH * SEQ * HS];
__device__ float g_k[Bsz * NH * SEQ * HS];
__device__ float g_v[Bsz * NH * SEQ * HS];
__device__ float g_att[M_TOT * EMB];

// ---------------------------------------------------------------------------
// Kernel 1: fused QKV projection.
// X[8192,1024] @ W[1024, 1024] per matrix, where W[e, j] = Wx[h, e, d],
// j = h*64+d. Output written directly in [B,H,S,HS] layout.
// Classic SIMT sgemm: BM=BN=128, BK=8, 256 threads, 8x8 micro-tile.
// ---------------------------------------------------------------------------
__global__ __launch_bounds__(256)
void qkv_gemm(const float* __restrict__ X,
              const float* __restrict__ Wq,
              const float* __restrict__ Wk,
              const float* __restrict__ Wv) {
    __shared__ float As[8][128];
    __shared__ float Bs[8][128];

    const int tid = threadIdx.x;
    const int tx = tid & 15, ty = tid >> 4;
    const int mat = blockIdx.x >> 3;            // 0=q 1=k 2=v
    const int n0 = (blockIdx.x & 7) * 128;
    const int m0 = blockIdx.y * 128;

    const float* W = (mat == 0) ? Wq : (mat == 1) ? Wk : Wv;
    float* out = (mat == 0) ? g_q : (mat == 1) ? g_k : g_v;

    const int arow = tid >> 1;          // 0..127
    const int acol = (tid & 1) * 4;     // 0 or 4
    const int brow = tid >> 5;          // 0..7
    const int bcol = (tid & 31) * 4;    // 0..124

    const int j_b = n0 + bcol;
    const int h_b = j_b >> 6, d_b = j_b & 63;

    float acc[8][8] = {};

    for (int k0 = 0; k0 < EMB; k0 += 8) {
        float4 av = *(const float4*)&X[(size_t)(m0 + arow) * EMB + k0 + acol];
        As[acol + 0][arow] = av.x;
        As[acol + 1][arow] = av.y;
        As[acol + 2][arow] = av.z;
        As[acol + 3][arow] = av.w;

        // W element (e = k0+brow, j = n0+bcol): Wx[h, e, d]
        float4 bv = *(const float4*)&W[(size_t)h_b * (EMB * HS) + (size_t)(k0 + brow) * HS + d_b];
        *(float4*)&Bs[brow][bcol] = bv;
        __syncthreads();

#pragma unroll
        for (int kk = 0; kk < 8; ++kk) {
            float a[8], b[8];
            *(float4*)&a[0] = *(const float4*)&As[kk][ty * 8];
            *(float4*)&a[4] = *(const float4*)&As[kk][ty * 8 + 4];
            *(float4*)&b[0] = *(const float4*)&Bs[kk][tx * 8];
            *(float4*)&b[4] = *(const float4*)&Bs[kk][tx * 8 + 4];
#pragma unroll
            for (int i = 0; i < 8; ++i)
#pragma unroll
                for (int jj = 0; jj < 8; ++jj)
                    acc[i][jj] += a[i] * b[jj];
        }
        __syncthreads();
    }

    // Epilogue: out[b,h,s,d]
#pragma unroll
    for (int i = 0; i < 8; ++i) {
        int m = m0 + ty * 8 + i;
        int b_ = m >> 10, s_ = m & 1023;
#pragma unroll
        for (int jj4 = 0; jj4 < 8; jj4 += 4) {
            int j = n0 + tx * 8 + jj4;
            int h_ = j >> 6, d_ = j & 63;
            float4 v4 = make_float4(acc[i][jj4], acc[i][jj4 + 1],
                                    acc[i][jj4 + 2], acc[i][jj4 + 3]);
            *(float4*)&out[((((size_t)b_ * NH + h_) * SEQ + s_) * HS + d_)] = v4;
        }
    }
}

// ---------------------------------------------------------------------------
// Kernel 2: causal flash attention, fp32.
// One block per (bh, q-tile of 64 rows). 256 threads as 16x16, 4x4 micro-tile.
// smem (dynamic, 51,968 B):
//   Qt [64 d][68]  - Q tile transposed (pad 68 keeps float4 align + low conflict)
//   Kt [64 d][68]  - K tile transposed; REUSED as Ss [64 r][65] (P matrix)
//   Vs [64 t][64]
//   m/l/scale[64]
// ---------------------------------------------------------------------------
#define ATTN_SMEM_FLOATS (64 * 68 + 64 * 68 + 64 * 64 + 3 * 64)
#define ATTN_SMEM_BYTES  (ATTN_SMEM_FLOATS * 4)

__global__ __launch_bounds__(256)
void attn_kernel() {
    extern __shared__ float sm[];
    float* Qt = sm;                 // [64][68]
    float* KtSs = Qt + 64 * 68;     // [64][68] as Kt, [64][65] as Ss
    float* Vs = KtSs + 64 * 68;     // [64][64]
    float* m_s = Vs + 64 * 64;      // [64]
    float* l_s = m_s + 64;          // [64]
    float* sc_s = l_s + 64;         // [64]

    const int tid = threadIdx.x;
    const int tx = tid & 15, ty = tid >> 4;
    const int qt = blockIdx.x;      // 0..15
    const int bh = blockIdx.y;      // 0..127

    const float* qsrc = g_q + ((size_t)bh * SEQ + (size_t)qt * 64) * HS;
    const float* ksrc = g_k + (size_t)bh * SEQ * HS;
    const float* vsrc = g_v + (size_t)bh * SEQ * HS;

    // Load Q tile transposed: Qt[d][r] = Q[r][d]
    for (int i = tid; i < 64 * 64; i += 256) {
        int d = i & 63, r = i >> 6;
        Qt[d * 68 + r] = qsrc[r * 64 + d];
    }
    if (tid < 64) { m_s[tid] = -INFINITY; l_s[tid] = 0.0f; }

    float o[4][4] = {};
    const float scale = 0.125f;  // HS^-0.5

    for (int jt = 0; jt <= qt; ++jt) {
        __syncthreads();  // prev-iter Ss/Vs consumers done before overwrite

        const float* kp = ksrc + (size_t)jt * 64 * 64;
        const float* vp = vsrc + (size_t)jt * 64 * 64;
        for (int i = tid; i < 64 * 64; i += 256) {
            int d = i & 63, r = i >> 6;
            KtSs[d * 68 + r] = kp[r * 64 + d];
        }
        for (int i = tid; i < 64 * 16; i += 256) {
            int t = i >> 4, d4 = (i & 15) * 4;
            *(float4*)&Vs[t * 64 + d4] = *(const float4*)&vp[t * 64 + d4];
        }
        __syncthreads();

        // S = Q @ K^T (rank-1 over d)
        float s[4][4] = {};
#pragma unroll 8
        for (int d = 0; d < 64; ++d) {
            float4 a4 = *(const float4*)&Qt[d * 68 + ty * 4];
            float4 b4 = *(const float4*)&KtSs[d * 68 + tx * 4];
            float a[4] = {a4.x, a4.y, a4.z, a4.w};
            float b[4] = {b4.x, b4.y, b4.z, b4.w};
#pragma unroll
            for (int i = 0; i < 4; ++i)
#pragma unroll
                for (int jj = 0; jj < 4; ++jj)
                    s[i][jj] += a[i] * b[jj];
        }
        __syncthreads();  // everyone done reading Kt before Ss overwrites it

        // Write scaled scores into Ss ([64][65], overlaps Kt region)
#pragma unroll
        for (int i = 0; i < 4; ++i)
#pragma unroll
            for (int jj = 0; jj < 4; ++jj)
                KtSs[(ty * 4 + i) * 65 + (tx * 4 + jj)] = s[i][jj] * scale;
        __syncthreads();

        // Online softmax: one thread per row
        if (tid < 64) {
            const int r = tid;
            const int nvalid = (jt == qt) ? (r + 1) : 64;
            float mold = m_s[r];
            float mx = mold;
            for (int c = 0; c < nvalid; ++c) mx = fmaxf(mx, KtSs[r * 65 + c]);
            float sc = expf(mold - mx);   // expf(-inf)=0 on first tile
            float sum = 0.0f;
            for (int c = 0; c < 64; ++c) {
                float p = (c < nvalid) ? expf(KtSs[r * 65 + c] - mx) : 0.0f;
                KtSs[r * 65 + c] = p;
                sum += p;
            }
            m_s[r] = mx;
            l_s[r] = l_s[r] * sc + sum;
            sc_s[r] = sc;
        }
        __syncthreads();

        // Rescale accumulator, then O += P @ V
        float scr[4];
#pragma unroll
        for (int i = 0; i < 4; ++i) scr[i] = sc_s[ty * 4 + i];
#pragma unroll
        for (int i = 0; i < 4; ++i)
#pragma unroll
            for (int jj = 0; jj < 4; ++jj)
                o[i][jj] *= scr[i];

#pragma unroll 8
        for (int t = 0; t < 64; ++t) {
            float4 v4 = *(const float4*)&Vs[t * 64 + tx * 4];
            float vb[4] = {v4.x, v4.y, v4.z, v4.w};
            float p[4];
#pragma unroll
            for (int i = 0; i < 4; ++i) p[i] = KtSs[(ty * 4 + i) * 65 + t];
#pragma unroll
            for (int i = 0; i < 4; ++i)
#pragma unroll
                for (int jj = 0; jj < 4; ++jj)
                    o[i][jj] += p[i] * vb[jj];
        }
    }

    // Final normalize + write to g_att in [B,S,H,HS] layout
    const int b_ = bh >> 4, h_ = bh & 15;
#pragma unroll
    for (int i = 0; i < 4; ++i) {
        int r = ty * 4 + i;
        float inv = 1.0f / l_s[r];
        int srow = qt * 64 + r;
        float4 v4 = make_float4(o[i][0] * inv, o[i][1] * inv,
                                o[i][2] * inv, o[i][3] * inv);
        *(float4*)&g_att[(((size_t)b_ * SEQ + srow) * NH + h_) * HS + tx * 4] = v4;
    }
}

// ---------------------------------------------------------------------------
// Kernel 3: output projection. out = g_att[8192,1024] @ Wproj^T + bproj.
// Wproj is [out, in] row-major -> NT GEMM (both operands K-contiguous).
// ---------------------------------------------------------------------------
__global__ __launch_bounds__(256)
void proj_gemm(const float* __restrict__ Wp,
               const float* __restrict__ bias,
               float* __restrict__ out) {
    __shared__ float As[8][128];
    __shared__ float Bs[8][128];

    const int tid = threadIdx.x;
    const int tx = tid & 15, ty = tid >> 4;
    const int n0 = blockIdx.x * 128;
    const int m0 = blockIdx.y * 128;

    const int arow = tid >> 1;
    const int acol = (tid & 1) * 4;
    const int bnn = tid >> 1;           // 0..127
    const int bkk = (tid & 1) * 4;      // 0 or 4

    float acc[8][8] = {};

    for (int k0 = 0; k0 < EMB; k0 += 8) {
        float4 av = *(const float4*)&g_att[(size_t)(m0 + arow) * EMB + k0 + acol];
        As[acol + 0][arow] = av.x;
        As[acol + 1][arow] = av.y;
        As[acol + 2][arow] = av.z;
        As[acol + 3][arow] = av.w;

        float4 wv = *(const float4*)&Wp[(size_t)(n0 + bnn) * EMB + k0 + bkk];
        Bs[bkk + 0][bnn] = wv.x;
        Bs[bkk + 1][bnn] = wv.y;
        Bs[bkk + 2][bnn] = wv.z;
        Bs[bkk + 3][bnn] = wv.w;
        __syncthreads();

#pragma unroll
        for (int kk = 0; kk < 8; ++kk) {
            float a[8], b[8];
            *(float4*)&a[0] = *(const float4*)&As[kk][ty * 8];
            *(float4*)&a[4] = *(const float4*)&As[kk][ty * 8 + 4];
            *(float4*)&b[0] = *(const float4*)&Bs[kk][tx * 8];
            *(float4*)&b[4] = *(const float4*)&Bs[kk][tx * 8 + 4];
#pragma unroll
            for (int i = 0; i < 8; ++i)
#pragma unroll
                for (int jj = 0; jj < 8; ++jj)
                    acc[i][jj] += a[i] * b[jj];
        }
        __syncthreads();
    }

#pragma unroll
    for (int i = 0; i < 8; ++i) {
        int m = m0 + ty * 8 + i;
#pragma unroll
        for (int jj4 = 0; jj4 < 8; jj4 += 4) {
            int n = n0 + tx * 8 + jj4;
            float4 bv = *(const float4*)&bias[n];
            float4 v4 = make_float4(acc[i][jj4] + bv.x, acc[i][jj4 + 1] + bv.y,
                                    acc[i][jj4 + 2] + bv.z, acc[i][jj4 + 3] + bv.w);
            *(float4*)&out[(size_t)m * EMB + n] = v4;
        }
    }
}

// ---------------------------------------------------------------------------
extern "C" void kernel_launch(void* const* d_in, const int* in_sizes, int n_in,
                              void* d_out, int out_size) {
    (void)in_sizes; (void)n_in; (void)out_size;
    const float* x     = (const float*)d_in[0];
    const float* Wq    = (const float*)d_in[1];
    const float* Wk    = (const float*)d_in[2];
    const float* Wv    = (const float*)d_in[3];
    const float* Wproj = (const float*)d_in[4];
    const float* bproj = (const float*)d_in[5];
    float* out = (float*)d_out;

    // Dynamic smem opt-in (idempotent, immediate; not a stream op -> capture-safe)
    cudaFuncSetAttribute(attn_kernel, cudaFuncAttributeMaxDynamicSharedMemorySize,
                         ATTN_SMEM_BYTES);

    qkv_gemm<<<dim3(24, 64), 256>>>(x, Wq, Wk, Wv);
    attn_kernel<<<dim3(16, Bsz * NH), 256, ATTN_SMEM_BYTES>>>();
    proj_gemm<<<dim3(8, 64), 256>>>(Wproj, bproj, out);
}

// round 3
// speedup vs baseline: 2.1705x; 2.1705x over previous
#include <cuda_runtime.h>
#include <math.h>
#include <stdint.h>

// Problem constants
#define Bsz 8
#define SEQ 1024
#define EMB 1024
#define NH  16
#define HS  64
#define M_TOT (Bsz * SEQ)   // 8192

// Scratch
__device__ float g_q[Bsz * NH * SEQ * HS];
__device__ float g_k[Bsz * NH * SEQ * HS];
__device__ float g_v[Bsz * NH * SEQ * HS];
__device__ float g_att[M_TOT * EMB];
__device__ float g_wt[3 * EMB * EMB];   // K-contiguous transposed QKV weights (tf32-rounded)
__device__ float g_xr[M_TOT * EMB];     // tf32-rounded X
__device__ float g_wpr[EMB * EMB];      // tf32-rounded Wproj

// ---------------------------------------------------------------------------
// Helpers
// ---------------------------------------------------------------------------
__device__ __forceinline__ uint32_t smem_u32(const void* p) {
    uint32_t a;
    asm("{ .reg .u64 t; cvta.to.shared.u64 t, %1; cvt.u32.u64 %0, t; }" : "=r"(a) : "l"(p));
    return a;
}
__device__ __forceinline__ float tf32_rna(float x) {
    uint32_t u;
    asm("cvt.rna.tf32.f32 %0, %1;" : "=r"(u) : "f"(x));
    return __uint_as_float(u);
}
#define CP_ASYNC16(dst, src) \
    asm volatile("cp.async.cg.shared.global [%0], [%1], 16;" :: "r"(dst), "l"(src))
#define CP_COMMIT() asm volatile("cp.async.commit_group;" ::: "memory")
#define CP_WAIT(n)  asm volatile("cp.async.wait_group %0;" :: "n"(n) : "memory")

__device__ __forceinline__ void mma_tf32(float* d, const uint32_t* a, const uint32_t* b) {
    asm volatile(
        "mma.sync.aligned.m16n8k8.row.col.f32.tf32.tf32.f32 "
        "{%0,%1,%2,%3}, {%4,%5,%6,%7}, {%8,%9}, {%0,%1,%2,%3};"
        : "+f"(d[0]), "+f"(d[1]), "+f"(d[2]), "+f"(d[3])
        : "r"(a[0]), "r"(a[1]), "r"(a[2]), "r"(a[3]), "r"(b[0]), "r"(b[1]));
}

// ---------------------------------------------------------------------------
// Rounding prep kernels
// ---------------------------------------------------------------------------
__global__ __launch_bounds__(256)
void round_tf32_kernel(const float* __restrict__ in, float* __restrict__ out) {
    size_t i = ((size_t)blockIdx.x * 256 + threadIdx.x) * 4;
    float4 v = *(const float4*)&in[i];
    v.x = tf32_rna(v.x); v.y = tf32_rna(v.y); v.z = tf32_rna(v.z); v.w = tf32_rna(v.w);
    *(float4*)&out[i] = v;
}

// Transpose QKV weights -> g_wt[mat][j=h*64+d][e] (K-contiguous), tf32-rounded.
__global__ __launch_bounds__(256)
void wt_transpose(const float* __restrict__ Wq,
                  const float* __restrict__ Wk,
                  const float* __restrict__ Wv) {
    __shared__ float t[64][65];
    const int tid = threadIdx.x;
    const int et = blockIdx.x;           // 16 e-tiles
    const int h  = blockIdx.y;           // 16 heads
    const int mat = blockIdx.z;          // 3
    const float* W = (mat == 0) ? Wq : (mat == 1) ? Wk : Wv;
    const float* src = W + (size_t)h * (EMB * HS) + (size_t)(et * 64) * HS;
    float* out = g_wt + (size_t)mat * (EMB * EMB);

    for (int i = tid; i < 64 * 64; i += 256) {
        int e = i >> 6, d = i & 63;
        t[e][d] = src[(size_t)e * HS + d];
    }
    __syncthreads();
    for (int i = tid; i < 64 * 64; i += 256) {
        int d = i >> 6, e = i & 63;
        out[(size_t)(h * 64 + d) * EMB + et * 64 + e] = tf32_rna(t[e][d]);
    }
}

// ---------------------------------------------------------------------------
// tf32 mma.sync GEMM core: C[128,128] = A[m0:,:1024] @ B[n0:,:1024]^T
// 256 threads = 8 warps in 2(m) x 4(n); warp tile 64x32; K-chunk 32.
// Smem per buffer: A[128][36], B[128][36] (stride 36 floats -> conflict-free).
// ---------------------------------------------------------------------------
#define LDF 36
#define TILE_F (128 * LDF)               // floats per A or B tile
#define BUF_BYTES (2 * TILE_F * 4)       // A+B one stage = 36864
#define MMA_SMEM_BYTES (2 * BUF_BYTES)   // 73728
#define NCHUNK (EMB / 32)

__device__ __forceinline__ void gemm_load_chunk(uint32_t base, int buf, int kc,
                                                const float* __restrict__ Ag,
                                                const float* __restrict__ Bg,
                                                int m0, int n0, int tid) {
    uint32_t a_s = base + (uint32_t)buf * BUF_BYTES;
    uint32_t b_s = a_s + TILE_F * 4;
    const float* ap = Ag + (size_t)m0 * EMB + kc * 32;
    const float* bp = Bg + (size_t)n0 * EMB + kc * 32;
#pragma unroll
    for (int i = 0; i < 4; ++i) {
        int idx = i * 256 + tid;
        int row = idx >> 3, c = idx & 7;
        CP_ASYNC16(a_s + row * (LDF * 4) + c * 16, ap + (size_t)row * EMB + c * 4);
    }
#pragma unroll
    for (int i = 0; i < 4; ++i) {
        int idx = i * 256 + tid;
        int row = idx >> 3, c = idx & 7;
        CP_ASYNC16(b_s + row * (LDF * 4) + c * 16, bp + (size_t)row * EMB + c * 4);
    }
    CP_COMMIT();
}

__device__ __forceinline__ void gemm_mainloop(char* smraw, uint32_t base,
                                              const float* __restrict__ Ag,
                                              const float* __restrict__ Bg,
                                              int m0, int n0,
                                              float acc[4][4][4]) {
    const int tid = threadIdx.x;
    const int wid = tid >> 5, lane = tid & 31;
    const int wm = wid & 1, wn = wid >> 1;
    const int r4 = lane >> 2, c4 = lane & 3;

    gemm_load_chunk(base, 0, 0, Ag, Bg, m0, n0, tid);
    gemm_load_chunk(base, 1, 1, Ag, Bg, m0, n0, tid);

    for (int kc = 0; kc < NCHUNK; ++kc) {
        if (kc + 1 < NCHUNK) { CP_WAIT(1); } else { CP_WAIT(0); }
        __syncthreads();

        const int buf = kc & 1;
        const float* As = (const float*)(smraw + (size_t)buf * BUF_BYTES);
        const float* Bs = As + TILE_F;

#pragma unroll
        for (int ks = 0; ks < 4; ++ks) {
            const int k0 = ks * 8;
            uint32_t af[4][4], bf[4][2];
#pragma unroll
            for (int mt = 0; mt < 4; ++mt) {
                int rb = (wm * 64 + mt * 16 + r4) * LDF + k0 + c4;
                af[mt][0] = *(const uint32_t*)&As[rb];
                af[mt][1] = *(const uint32_t*)&As[rb + 8 * LDF];
                af[mt][2] = *(const uint32_t*)&As[rb + 4];
                af[mt][3] = *(const uint32_t*)&As[rb + 8 * LDF + 4];
            }
#pragma unroll
            for (int nt = 0; nt < 4; ++nt) {
                int nb = (wn * 32 + nt * 8 + r4) * LDF + k0 + c4;
                bf[nt][0] = *(const uint32_t*)&Bs[nb];
                bf[nt][1] = *(const uint32_t*)&Bs[nb + 4];
            }
#pragma unroll
            for (int mt = 0; mt < 4; ++mt)
#pragma unroll
                for (int nt = 0; nt < 4; ++nt)
                    mma_tf32(acc[mt][nt], af[mt], bf[nt]);
        }
        __syncthreads();
        if (kc + 2 < NCHUNK)
            gemm_load_chunk(base, buf, kc + 2, Ag, Bg, m0, n0, tid);
    }
}

// ---------------------------------------------------------------------------
// Kernel 1: QKV projection. Grid (24, 64): x = mat*8 + ntile, y = mtile.
// ---------------------------------------------------------------------------
__global__ __launch_bounds__(256)
void qkv_mma(void) {
    extern __shared__ char sm[];
    uint32_t base = smem_u32(sm);
    const int tid = threadIdx.x;
    const int wid = tid >> 5, lane = tid & 31;
    const int wm = wid & 1, wn = wid >> 1;
    const int r4 = lane >> 2, c4 = lane & 3;
    const int mat = blockIdx.x >> 3;
    const int n0 = (blockIdx.x & 7) * 128;
    const int m0 = blockIdx.y * 128;
    float* out = (mat == 0) ? g_q : (mat == 1) ? g_k : g_v;
    const float* Bg = g_wt + (size_t)mat * (EMB * EMB);

    float acc[4][4][4] = {};
    gemm_mainloop(sm, base, g_xr, Bg, m0, n0, acc);

    // Epilogue: out[b,h,s,d], n = h*64+d
#pragma unroll
    for (int mt = 0; mt < 4; ++mt) {
#pragma unroll
        for (int nt = 0; nt < 4; ++nt) {
            int n = n0 + wn * 32 + nt * 8 + c4 * 2;
            int h_ = n >> 6, d_ = n & 63;
#pragma unroll
            for (int rr = 0; rr < 2; ++rr) {
                int m = m0 + wm * 64 + mt * 16 + r4 + rr * 8;
                int b_ = m >> 10, s_ = m & 1023;
                float2 v = make_float2(acc[mt][nt][rr * 2], acc[mt][nt][rr * 2 + 1]);
                *(float2*)&out[(((size_t)b_ * NH + h_) * SEQ + s_) * HS + d_] = v;
            }
        }
    }
}

// ---------------------------------------------------------------------------
// Kernel 3: output projection. out = g_att @ Wproj^T + b. Grid (8, 64).
// ---------------------------------------------------------------------------
__global__ __launch_bounds__(256)
void proj_mma(const float* __restrict__ bias, float* __restrict__ out) {
    extern __shared__ char sm[];
    uint32_t base = smem_u32(sm);
    const int tid = threadIdx.x;
    const int wid = tid >> 5, lane = tid & 31;
    const int wm = wid & 1, wn = wid >> 1;
    const int r4 = lane >> 2, c4 = lane & 3;
    const int n0 = blockIdx.x * 128;
    const int m0 = blockIdx.y * 128;

    float acc[4][4][4] = {};
    gemm_mainloop(sm, base, g_att, g_wpr, m0, n0, acc);

#pragma unroll
    for (int mt = 0; mt < 4; ++mt) {
#pragma unroll
        for (int nt = 0; nt < 4; ++nt) {
            int n = n0 + wn * 32 + nt * 8 + c4 * 2;
            float2 bv = *(const float2*)&bias[n];
#pragma unroll
            for (int rr = 0; rr < 2; ++rr) {
                int m = m0 + wm * 64 + mt * 16 + r4 + rr * 8;
                float2 v = make_float2(acc[mt][nt][rr * 2] + bv.x,
                                       acc[mt][nt][rr * 2 + 1] + bv.y);
                *(float2*)&out[(size_t)m * EMB + n] = v;
            }
        }
    }
}

// ---------------------------------------------------------------------------
// Kernel 2: causal flash attention, fp32 SIMT, parallel softmax.
// ---------------------------------------------------------------------------
#define ATTN_SMEM_FLOATS (64 * 68 + 64 * 68 + 64 * 64 + 3 * 64)
#define ATTN_SMEM_BYTES  (ATTN_SMEM_FLOATS * 4)

__global__ __launch_bounds__(256)
void attn_kernel() {
    extern __shared__ float smf[];
    float* Qt = smf;                 // [64][68]
    float* KtSs = Qt + 64 * 68;      // Kt [64][68] / Ss [64][65]
    float* Vs = KtSs + 64 * 68;      // [64][64]
    float* m_s = Vs + 64 * 64;
    float* l_s = m_s + 64;
    float* sc_s = l_s + 64;

    const int tid = threadIdx.x;
    const int tx = tid & 15, ty = tid >> 4;
    const int qt = blockIdx.x;
    const int bh = blockIdx.y;

    const float* qsrc = g_q + ((size_t)bh * SEQ + (size_t)qt * 64) * HS;
    const float* ksrc = g_k + (size_t)bh * SEQ * HS;
    const float* vsrc = g_v + (size_t)bh * SEQ * HS;

    for (int i = tid; i < 64 * 64; i += 256) {
        int d = i & 63, r = i >> 6;
        Qt[d * 68 + r] = qsrc[r * 64 + d];
    }
    if (tid < 64) { m_s[tid] = -INFINITY; l_s[tid] = 0.0f; }

    float o[4][4] = {};
    const float scale = 0.125f;

    for (int jt = 0; jt <= qt; ++jt) {
        __syncthreads();
        const float* kp = ksrc + (size_t)jt * 64 * 64;
        const float* vp = vsrc + (size_t)jt * 64 * 64;
        for (int i = tid; i < 64 * 64; i += 256) {
            int d = i & 63, r = i >> 6;
            KtSs[d * 68 + r] = kp[r * 64 + d];
        }
        for (int i = tid; i < 64 * 16; i += 256) {
            int t = i >> 4, d4 = (i & 15) * 4;
            *(float4*)&Vs[t * 64 + d4] = *(const float4*)&vp[t * 64 + d4];
        }
        __syncthreads();

        float s[4][4] = {};
#pragma unroll 8
        for (int d = 0; d < 64; ++d) {
            float4 a4 = *(const float4*)&Qt[d * 68 + ty * 4];
            float4 b4 = *(const float4*)&KtSs[d * 68 + tx * 4];
            float a[4] = {a4.x, a4.y, a4.z, a4.w};
            float b[4] = {b4.x, b4.y, b4.z, b4.w};
#pragma unroll
            for (int i = 0; i < 4; ++i)
#pragma unroll
                for (int jj = 0; jj < 4; ++jj)
                    s[i][jj] += a[i] * b[jj];
        }
        __syncthreads();

#pragma unroll
        for (int i = 0; i < 4; ++i)
#pragma unroll
            for (int jj = 0; jj < 4; ++jj)
                KtSs[(ty * 4 + i) * 65 + (tx * 4 + jj)] = s[i][jj] * scale;
        __syncthreads();

        // Parallel online softmax: 4 lanes per row (lanes of a row share a warp)
        {
            const int r = tid >> 2, q = tid & 3;
            const int nvalid = (jt == qt) ? (r + 1) : 64;
            const int cb = q * 16;
            float mold = m_s[r];
            float lold = l_s[r];
            float mx = mold;
#pragma unroll
            for (int c = 0; c < 16; ++c) {
                int cc = cb + c;
                float v = KtSs[r * 65 + cc];
                if (cc < nvalid) mx = fmaxf(mx, v);
            }
            mx = fmaxf(mx, __shfl_xor_sync(0xFFFFFFFFu, mx, 1));
            mx = fmaxf(mx, __shfl_xor_sync(0xFFFFFFFFu, mx, 2));
            float sum = 0.0f;
#pragma unroll
            for (int c = 0; c < 16; ++c) {
                int cc = cb + c;
                float p = (cc < nvalid) ? __expf(KtSs[r * 65 + cc] - mx) : 0.0f;
                KtSs[r * 65 + cc] = p;
                sum += p;
            }
            sum += __shfl_xor_sync(0xFFFFFFFFu, sum, 1);
            sum += __shfl_xor_sync(0xFFFFFFFFu, sum, 2);
            if (q == 0) {
                float sc = __expf(mold - mx);
                m_s[r] = mx;
                l_s[r] = lold * sc + sum;
                sc_s[r] = sc;
            }
        }
        __syncthreads();

        float scr[4];
#pragma unroll
        for (int i = 0; i < 4; ++i) scr[i] = sc_s[ty * 4 + i];
#pragma unroll
        for (int i = 0; i < 4; ++i)
#pragma unroll
            for (int jj = 0; jj < 4; ++jj)
                o[i][jj] *= scr[i];

#pragma unroll 8
        for (int t = 0; t < 64; ++t) {
            float4 v4 = *(const float4*)&Vs[t * 64 + tx * 4];
            float vb[4] = {v4.x, v4.y, v4.z, v4.w};
            float p[4];
#pragma unroll
            for (int i = 0; i < 4; ++i) p[i] = KtSs[(ty * 4 + i) * 65 + t];
#pragma unroll
            for (int i = 0; i < 4; ++i)
#pragma unroll
                for (int jj = 0; jj < 4; ++jj)
                    o[i][jj] += p[i] * vb[jj];
        }
    }

    // Final normalize + tf32-round + write [B,S,H,HS]
    const int b_ = bh >> 4, h_ = bh & 15;
#pragma unroll
    for (int i = 0; i < 4; ++i) {
        int r = ty * 4 + i;
        float inv = 1.0f / l_s[r];
        int srow = qt * 64 + r;
        float4 v4 = make_float4(tf32_rna(o[i][0] * inv), tf32_rna(o[i][1] * inv),
                                tf32_rna(o[i][2] * inv), tf32_rna(o[i][3] * inv));
        *(float4*)&g_att[(((size_t)b_ * SEQ + srow) * NH + h_) * HS + tx * 4] = v4;
    }
}

// ---------------------------------------------------------------------------
extern "C" void kernel_launch(void* const* d_in, const int* in_sizes, int n_in,
                              void* d_out, int out_size) {
    (void)in_sizes; (void)n_in; (void)out_size;
    const float* x     = (const float*)d_in[0];
    const float* Wq    = (const float*)d_in[1];
    const float* Wk    = (const float*)d_in[2];
    const float* Wv    = (const float*)d_in[3];
    const float* Wproj = (const float*)d_in[4];
    const float* bproj = (const float*)d_in[5];
    float* out = (float*)d_out;

    cudaFuncSetAttribute(qkv_mma, cudaFuncAttributeMaxDynamicSharedMemorySize, MMA_SMEM_BYTES);
    cudaFuncSetAttribute(proj_mma, cudaFuncAttributeMaxDynamicSharedMemorySize, MMA_SMEM_BYTES);
    cudaFuncSetAttribute(attn_kernel, cudaFuncAttributeMaxDynamicSharedMemorySize, ATTN_SMEM_BYTES);

    float* p_xr = nullptr;  cudaGetSymbolAddress((void**)&p_xr, g_xr);
    float* p_wpr = nullptr; cudaGetSymbolAddress((void**)&p_wpr, g_wpr);

    round_tf32_kernel<<<M_TOT * EMB / 1024, 256>>>(x, p_xr);
    round_tf32_kernel<<<EMB * EMB / 1024, 256>>>(Wproj, p_wpr);
    wt_transpose<<<dim3(16, 16, 3), 256>>>(Wq, Wk, Wv);
    qkv_mma<<<dim3(24, 64), 256, MMA_SMEM_BYTES>>>();
    attn_kernel<<<dim3(16, Bsz * NH), 256, ATTN_SMEM_BYTES>>>();
    proj_mma<<<dim3(8, 64), 256, MMA_SMEM_BYTES>>>(bproj, out);
}

// round 4
// speedup vs baseline: 2.2186x; 1.0221x over previous
#include <cuda_runtime.h>
#include <math.h>
#include <stdint.h>

// Problem constants
#define Bsz 8
#define SEQ 1024
#define EMB 1024
#define NH  16
#define HS  64
#define M_TOT (Bsz * SEQ)   // 8192

// Scratch
__device__ float g_q[Bsz * NH * SEQ * HS];
__device__ float g_k[Bsz * NH * SEQ * HS];
__device__ float g_v[Bsz * NH * SEQ * HS];
__device__ float g_att[M_TOT * EMB];
__device__ float g_wt[3 * EMB * EMB];   // K-contiguous transposed QKV weights (tf32-rounded)
__device__ float g_xr[M_TOT * EMB];     // tf32-rounded X
__device__ float g_wpr[EMB * EMB];      // tf32-rounded Wproj

// ---------------------------------------------------------------------------
// Helpers
// ---------------------------------------------------------------------------
__device__ __forceinline__ uint32_t smem_u32(const void* p) {
    uint32_t a;
    asm("{ .reg .u64 t; cvta.to.shared.u64 t, %1; cvt.u32.u64 %0, t; }" : "=r"(a) : "l"(p));
    return a;
}
__device__ __forceinline__ float tf32_rna(float x) {
    uint32_t u;
    asm("cvt.rna.tf32.f32 %0, %1;" : "=r"(u) : "f"(x));
    return __uint_as_float(u);
}
#define CP_ASYNC16(dst, src) \
    asm volatile("cp.async.cg.shared.global [%0], [%1], 16;" :: "r"(dst), "l"(src))
#define CP_COMMIT() asm volatile("cp.async.commit_group;" ::: "memory")
#define CP_WAIT(n)  asm volatile("cp.async.wait_group %0;" :: "n"(n) : "memory")

__device__ __forceinline__ void mma_tf32(float* d, const uint32_t* a, const uint32_t* b) {
    asm volatile(
        "mma.sync.aligned.m16n8k8.row.col.f32.tf32.tf32.f32 "
        "{%0,%1,%2,%3}, {%4,%5,%6,%7}, {%8,%9}, {%0,%1,%2,%3};"
        : "+f"(d[0]), "+f"(d[1]), "+f"(d[2]), "+f"(d[3])
        : "r"(a[0]), "r"(a[1]), "r"(a[2]), "r"(a[3]), "r"(b[0]), "r"(b[1]));
}

// ---------------------------------------------------------------------------
// Rounding prep kernels
// ---------------------------------------------------------------------------
__global__ __launch_bounds__(256)
void round_tf32_kernel(const float* __restrict__ in, float* __restrict__ out) {
    size_t i = ((size_t)blockIdx.x * 256 + threadIdx.x) * 4;
    float4 v = *(const float4*)&in[i];
    v.x = tf32_rna(v.x); v.y = tf32_rna(v.y); v.z = tf32_rna(v.z); v.w = tf32_rna(v.w);
    *(float4*)&out[i] = v;
}

__global__ __launch_bounds__(256)
void wt_transpose(const float* __restrict__ Wq,
                  const float* __restrict__ Wk,
                  const float* __restrict__ Wv) {
    __shared__ float t[64][65];
    const int tid = threadIdx.x;
    const int et = blockIdx.x;
    const int h  = blockIdx.y;
    const int mat = blockIdx.z;
    const float* W = (mat == 0) ? Wq : (mat == 1) ? Wk : Wv;
    const float* src = W + (size_t)h * (EMB * HS) + (size_t)(et * 64) * HS;
    float* out = g_wt + (size_t)mat * (EMB * EMB);

    for (int i = tid; i < 64 * 64; i += 256) {
        int e = i >> 6, d = i & 63;
        t[e][d] = src[(size_t)e * HS + d];
    }
    __syncthreads();
    for (int i = tid; i < 64 * 64; i += 256) {
        int d = i >> 6, e = i & 63;
        out[(size_t)(h * 64 + d) * EMB + et * 64 + e] = tf32_rna(t[e][d]);
    }
}

// ---------------------------------------------------------------------------
// tf32 mma.sync GEMM core (unchanged from R3): C[128,128] = A @ B^T
// ---------------------------------------------------------------------------
#define LDF 36
#define TILE_F (128 * LDF)
#define BUF_BYTES (2 * TILE_F * 4)
#define MMA_SMEM_BYTES (2 * BUF_BYTES)
#define NCHUNK (EMB / 32)

__device__ __forceinline__ void gemm_load_chunk(uint32_t base, int buf, int kc,
                                                const float* __restrict__ Ag,
                                                const float* __restrict__ Bg,
                                                int m0, int n0, int tid) {
    uint32_t a_s = base + (uint32_t)buf * BUF_BYTES;
    uint32_t b_s = a_s + TILE_F * 4;
    const float* ap = Ag + (size_t)m0 * EMB + kc * 32;
    const float* bp = Bg + (size_t)n0 * EMB + kc * 32;
#pragma unroll
    for (int i = 0; i < 4; ++i) {
        int idx = i * 256 + tid;
        int row = idx >> 3, c = idx & 7;
        CP_ASYNC16(a_s + row * (LDF * 4) + c * 16, ap + (size_t)row * EMB + c * 4);
    }
#pragma unroll
    for (int i = 0; i < 4; ++i) {
        int idx = i * 256 + tid;
        int row = idx >> 3, c = idx & 7;
        CP_ASYNC16(b_s + row * (LDF * 4) + c * 16, bp + (size_t)row * EMB + c * 4);
    }
    CP_COMMIT();
}

__device__ __forceinline__ void gemm_mainloop(char* smraw, uint32_t base,
                                              const float* __restrict__ Ag,
                                              const float* __restrict__ Bg,
                                              int m0, int n0,
                                              float acc[4][4][4]) {
    const int tid = threadIdx.x;
    const int wid = tid >> 5, lane = tid & 31;
    const int wm = wid & 1, wn = wid >> 1;
    const int r4 = lane >> 2, c4 = lane & 3;

    gemm_load_chunk(base, 0, 0, Ag, Bg, m0, n0, tid);
    gemm_load_chunk(base, 1, 1, Ag, Bg, m0, n0, tid);

    for (int kc = 0; kc < NCHUNK; ++kc) {
        if (kc + 1 < NCHUNK) { CP_WAIT(1); } else { CP_WAIT(0); }
        __syncthreads();

        const int buf = kc & 1;
        const float* As = (const float*)(smraw + (size_t)buf * BUF_BYTES);
        const float* Bs = As + TILE_F;

#pragma unroll
        for (int ks = 0; ks < 4; ++ks) {
            const int k0 = ks * 8;
            uint32_t af[4][4], bf[4][2];
#pragma unroll
            for (int mt = 0; mt < 4; ++mt) {
                int rb = (wm * 64 + mt * 16 + r4) * LDF + k0 + c4;
                af[mt][0] = *(const uint32_t*)&As[rb];
                af[mt][1] = *(const uint32_t*)&As[rb + 8 * LDF];
                af[mt][2] = *(const uint32_t*)&As[rb + 4];
                af[mt][3] = *(const uint32_t*)&As[rb + 8 * LDF + 4];
            }
#pragma unroll
            for (int nt = 0; nt < 4; ++nt) {
                int nb = (wn * 32 + nt * 8 + r4) * LDF + k0 + c4;
                bf[nt][0] = *(const uint32_t*)&Bs[nb];
                bf[nt][1] = *(const uint32_t*)&Bs[nb + 4];
            }
#pragma unroll
            for (int mt = 0; mt < 4; ++mt)
#pragma unroll
                for (int nt = 0; nt < 4; ++nt)
                    mma_tf32(acc[mt][nt], af[mt], bf[nt]);
        }
        __syncthreads();
        if (kc + 2 < NCHUNK)
            gemm_load_chunk(base, buf, kc + 2, Ag, Bg, m0, n0, tid);
    }
}

__global__ __launch_bounds__(256)
void qkv_mma(void) {
    extern __shared__ char sm[];
    uint32_t base = smem_u32(sm);
    const int tid = threadIdx.x;
    const int wid = tid >> 5, lane = tid & 31;
    const int wm = wid & 1, wn = wid >> 1;
    const int r4 = lane >> 2, c4 = lane & 3;
    const int mat = blockIdx.x >> 3;
    const int n0 = (blockIdx.x & 7) * 128;
    const int m0 = blockIdx.y * 128;
    float* out = (mat == 0) ? g_q : (mat == 1) ? g_k : g_v;
    const float* Bg = g_wt + (size_t)mat * (EMB * EMB);

    float acc[4][4][4] = {};
    gemm_mainloop(sm, base, g_xr, Bg, m0, n0, acc);

#pragma unroll
    for (int mt = 0; mt < 4; ++mt) {
#pragma unroll
        for (int nt = 0; nt < 4; ++nt) {
            int n = n0 + wn * 32 + nt * 8 + c4 * 2;
            int h_ = n >> 6, d_ = n & 63;
#pragma unroll
            for (int rr = 0; rr < 2; ++rr) {
                int m = m0 + wm * 64 + mt * 16 + r4 + rr * 8;
                int b_ = m >> 10, s_ = m & 1023;
                float2 v = make_float2(acc[mt][nt][rr * 2], acc[mt][nt][rr * 2 + 1]);
                *(float2*)&out[(((size_t)b_ * NH + h_) * SEQ + s_) * HS + d_] = v;
            }
        }
    }
}

__global__ __launch_bounds__(256)
void proj_mma(const float* __restrict__ bias, float* __restrict__ out) {
    extern __shared__ char sm[];
    uint32_t base = smem_u32(sm);
    const int tid = threadIdx.x;
    const int wid = tid >> 5, lane = tid & 31;
    const int wm = wid & 1, wn = wid >> 1;
    const int r4 = lane >> 2, c4 = lane & 3;
    const int n0 = blockIdx.x * 128;
    const int m0 = blockIdx.y * 128;

    float acc[4][4][4] = {};
    gemm_mainloop(sm, base, g_att, g_wpr, m0, n0, acc);

#pragma unroll
    for (int mt = 0; mt < 4; ++mt) {
#pragma unroll
        for (int nt = 0; nt < 4; ++nt) {
            int n = n0 + wn * 32 + nt * 8 + c4 * 2;
            float2 bv = *(const float2*)&bias[n];
#pragma unroll
            for (int rr = 0; rr < 2; ++rr) {
                int m = m0 + wm * 64 + mt * 16 + r4 + rr * 8;
                float2 v = make_float2(acc[mt][nt][rr * 2] + bv.x,
                                       acc[mt][nt][rr * 2 + 1] + bv.y);
                *(float2*)&out[(size_t)m * EMB + n] = v;
            }
        }
    }
}

// ---------------------------------------------------------------------------
// Kernel 2: causal flash attention, tf32 mma.sync (FA2-style).
// Grid (8 qtiles of 128 rows, 128 bh). 256 threads = 8 warps x 16 rows.
// S = Q@K^T in double-tf32 (hi+lo, 3 MMAs); P@V single tf32.
// Smem: Qhi/Qlo[128][68], Khi/Klo[64][68], Vt[64][68], Ps[128][68].
// ---------------------------------------------------------------------------
#define ALD 68
#define ATTN_SMEM_FLOATS (128*ALD*2 + 64*ALD*2 + 64*ALD + 128*ALD)
#define ATTN_SMEM_BYTES  (ATTN_SMEM_FLOATS * 4)   // 156,672

__global__ __launch_bounds__(256)
void attn_mma() {
    extern __shared__ float sf[];
    float* Qhi = sf;
    float* Qlo = Qhi + 128 * ALD;
    float* Khi = Qlo + 128 * ALD;
    float* Klo = Khi + 64 * ALD;
    float* Vt  = Klo + 64 * ALD;
    float* Ps  = Vt  + 64 * ALD;

    const int tid = threadIdx.x;
    const int w = tid >> 5, lane = tid & 31;
    const int r4 = lane >> 2, c4 = lane & 3;
    const int qt = blockIdx.x;      // 0..7 (128-row q tiles)
    const int bh = blockIdx.y;      // 0..127

    const float* qsrc = g_q + ((size_t)bh * SEQ + (size_t)qt * 128) * HS;
    const float* ksrc = g_k + (size_t)bh * SEQ * HS;
    const float* vsrc = g_v + (size_t)bh * SEQ * HS;

    // Load Q (128x64), fold in softmax scale, split hi/lo tf32.
    const float scale = 0.125f;
    for (int i = tid * 4; i < 128 * 64; i += 1024) {
        int row = i >> 6, col = i & 63;
        float4 qv = *(const float4*)&qsrc[i];
        float vals[4] = {qv.x * scale, qv.y * scale, qv.z * scale, qv.w * scale};
#pragma unroll
        for (int j = 0; j < 4; ++j) {
            float hi = tf32_rna(vals[j]);
            Qhi[row * ALD + col + j] = hi;
            Qlo[row * ALD + col + j] = tf32_rna(vals[j] - hi);
        }
    }

    float m0 = -1e30f, m1 = -1e30f, l0 = 0.0f, l1 = 0.0f;
    float o[8][4] = {};

    const int jmax = 2 * qt + 1;
    for (int jt = 0; jt <= jmax; ++jt) {
        __syncthreads();   // prior-iter consumers of K/V done before overwrite

        const float* kp = ksrc + (size_t)jt * 64 * 64;
        const float* vp = vsrc + (size_t)jt * 64 * 64;
        for (int i = tid * 4; i < 64 * 64; i += 1024) {
            int t = i >> 6, d = i & 63;
            float4 kv4 = *(const float4*)&kp[i];
            float vals[4] = {kv4.x, kv4.y, kv4.z, kv4.w};
#pragma unroll
            for (int j = 0; j < 4; ++j) {
                float hi = tf32_rna(vals[j]);
                Khi[t * ALD + d + j] = hi;
                Klo[t * ALD + d + j] = tf32_rna(vals[j] - hi);
            }
        }
        for (int i = tid; i < 64 * 64; i += 256) {
            int t = i >> 6, d = i & 63;
            Vt[d * ALD + t] = tf32_rna(vp[i]);
        }
        __syncthreads();

        // --- S = Q@K^T (double-tf32), warp rows w*16..w*16+15 ---
        float sacc[8][4] = {};
#pragma unroll
        for (int ks = 0; ks < 8; ++ks) {
            const int k0 = ks * 8;
            uint32_t ah[4], al[4];
            int ra = (w * 16 + r4) * ALD + k0 + c4;
            ah[0] = *(const uint32_t*)&Qhi[ra];
            ah[1] = *(const uint32_t*)&Qhi[ra + 8 * ALD];
            ah[2] = *(const uint32_t*)&Qhi[ra + 4];
            ah[3] = *(const uint32_t*)&Qhi[ra + 8 * ALD + 4];
            al[0] = *(const uint32_t*)&Qlo[ra];
            al[1] = *(const uint32_t*)&Qlo[ra + 8 * ALD];
            al[2] = *(const uint32_t*)&Qlo[ra + 4];
            al[3] = *(const uint32_t*)&Qlo[ra + 8 * ALD + 4];
#pragma unroll
            for (int nt = 0; nt < 8; ++nt) {
                int rb = (nt * 8 + r4) * ALD + k0 + c4;
                uint32_t bh_[2], bl_[2];
                bh_[0] = *(const uint32_t*)&Khi[rb];
                bh_[1] = *(const uint32_t*)&Khi[rb + 4];
                bl_[0] = *(const uint32_t*)&Klo[rb];
                bl_[1] = *(const uint32_t*)&Klo[rb + 4];
                mma_tf32(sacc[nt], ah, bh_);
                mma_tf32(sacc[nt], ah, bl_);
                mma_tf32(sacc[nt], al, bh_);
            }
        }

        // --- causal mask on diagonal tiles ---
        if (jt >= 2 * qt) {
            int rg0 = qt * 128 + w * 16 + r4;
#pragma unroll
            for (int nt = 0; nt < 8; ++nt) {
                int cg = jt * 64 + nt * 8 + c4 * 2;
                if (cg > rg0)     sacc[nt][0] = -1e30f;
                if (cg + 1 > rg0) sacc[nt][1] = -1e30f;
                if (cg > rg0 + 8)     sacc[nt][2] = -1e30f;
                if (cg + 1 > rg0 + 8) sacc[nt][3] = -1e30f;
            }
        }

        // --- online softmax (register, per-row via quad shfl) ---
        float mx0 = m0, mx1 = m1;
#pragma unroll
        for (int nt = 0; nt < 8; ++nt) {
            mx0 = fmaxf(mx0, fmaxf(sacc[nt][0], sacc[nt][1]));
            mx1 = fmaxf(mx1, fmaxf(sacc[nt][2], sacc[nt][3]));
        }
        mx0 = fmaxf(mx0, __shfl_xor_sync(0xFFFFFFFFu, mx0, 1));
        mx0 = fmaxf(mx0, __shfl_xor_sync(0xFFFFFFFFu, mx0, 2));
        mx1 = fmaxf(mx1, __shfl_xor_sync(0xFFFFFFFFu, mx1, 1));
        mx1 = fmaxf(mx1, __shfl_xor_sync(0xFFFFFFFFu, mx1, 2));
        float a0 = __expf(m0 - mx0);
        float a1 = __expf(m1 - mx1);
        m0 = mx0; m1 = mx1;

        float s0 = 0.0f, s1 = 0.0f;
        {
            int row0 = (w * 16 + r4) * ALD;
            int row1 = row0 + 8 * ALD;
#pragma unroll
            for (int nt = 0; nt < 8; ++nt) {
                int cl = nt * 8 + c4 * 2;
                float p00 = tf32_rna(__expf(sacc[nt][0] - mx0));
                float p01 = tf32_rna(__expf(sacc[nt][1] - mx0));
                float p10 = tf32_rna(__expf(sacc[nt][2] - mx1));
                float p11 = tf32_rna(__expf(sacc[nt][3] - mx1));
                s0 += p00 + p01;
                s1 += p10 + p11;
                *(float2*)&Ps[row0 + cl] = make_float2(p00, p01);
                *(float2*)&Ps[row1 + cl] = make_float2(p10, p11);
            }
        }
        s0 += __shfl_xor_sync(0xFFFFFFFFu, s0, 1);
        s0 += __shfl_xor_sync(0xFFFFFFFFu, s0, 2);
        s1 += __shfl_xor_sync(0xFFFFFFFFu, s1, 1);
        s1 += __shfl_xor_sync(0xFFFFFFFFu, s1, 2);
        l0 = l0 * a0 + s0;
        l1 = l1 * a1 + s1;

        // rescale O
#pragma unroll
        for (int nt = 0; nt < 8; ++nt) {
            o[nt][0] *= a0; o[nt][1] *= a0;
            o[nt][2] *= a1; o[nt][3] *= a1;
        }
        __syncwarp();   // Ps rows of this warp visible to its own lanes

        // --- O += P @ V ---
#pragma unroll
        for (int ks = 0; ks < 8; ++ks) {
            const int k0 = ks * 8;
            uint32_t af[4];
            int ra = (w * 16 + r4) * ALD + k0 + c4;
            af[0] = *(const uint32_t*)&Ps[ra];
            af[1] = *(const uint32_t*)&Ps[ra + 8 * ALD];
            af[2] = *(const uint32_t*)&Ps[ra + 4];
            af[3] = *(const uint32_t*)&Ps[ra + 8 * ALD + 4];
#pragma unroll
            for (int nt = 0; nt < 8; ++nt) {
                int rb = (nt * 8 + r4) * ALD + k0 + c4;
                uint32_t bf[2];
                bf[0] = *(const uint32_t*)&Vt[rb];
                bf[1] = *(const uint32_t*)&Vt[rb + 4];
                mma_tf32(o[nt], af, bf);
            }
        }
    }

    // Epilogue: normalize, tf32-round, write g_att [B,S,H,HS]
    const int b_ = bh >> 4, h_ = bh & 15;
    const float inv0 = 1.0f / l0, inv1 = 1.0f / l1;
    const int row0 = qt * 128 + w * 16 + r4;
#pragma unroll
    for (int nt = 0; nt < 8; ++nt) {
        int d = nt * 8 + c4 * 2;
        float2 v0 = make_float2(tf32_rna(o[nt][0] * inv0), tf32_rna(o[nt][1] * inv0));
        float2 v1 = make_float2(tf32_rna(o[nt][2] * inv1), tf32_rna(o[nt][3] * inv1));
        *(float2*)&g_att[(((size_t)b_ * SEQ + row0) * NH + h_) * HS + d] = v0;
        *(float2*)&g_att[(((size_t)b_ * SEQ + row0 + 8) * NH + h_) * HS + d] = v1;
    }
}

// ---------------------------------------------------------------------------
extern "C" void kernel_launch(void* const* d_in, const int* in_sizes, int n_in,
                              void* d_out, int out_size) {
    (void)in_sizes; (void)n_in; (void)out_size;
    const float* x     = (const float*)d_in[0];
    const float* Wq    = (const float*)d_in[1];
    const float* Wk    = (const float*)d_in[2];
    const float* Wv    = (const float*)d_in[3];
    const float* Wproj = (const float*)d_in[4];
    const float* bproj = (const float*)d_in[5];
    float* out = (float*)d_out;

    cudaFuncSetAttribute(qkv_mma, cudaFuncAttributeMaxDynamicSharedMemorySize, MMA_SMEM_BYTES);
    cudaFuncSetAttribute(proj_mma, cudaFuncAttributeMaxDynamicSharedMemorySize, MMA_SMEM_BYTES);
    cudaFuncSetAttribute(attn_mma, cudaFuncAttributeMaxDynamicSharedMemorySize, ATTN_SMEM_BYTES);

    float* p_xr = nullptr;  cudaGetSymbolAddress((void**)&p_xr, g_xr);
    float* p_wpr = nullptr; cudaGetSymbolAddress((void**)&p_wpr, g_wpr);

    round_tf32_kernel<<<M_TOT * EMB / 1024, 256>>>(x, p_xr);
    round_tf32_kernel<<<EMB * EMB / 1024, 256>>>(Wproj, p_wpr);
    wt_transpose<<<dim3(16, 16, 3), 256>>>(Wq, Wk, Wv);
    qkv_mma<<<dim3(24, 64), 256, MMA_SMEM_BYTES>>>();
    attn_mma<<<dim3(8, Bsz * NH), 256, ATTN_SMEM_BYTES>>>();
    proj_mma<<<dim3(8, 64), 256, MMA_SMEM_BYTES>>>(bproj, out);
}

// round 5
// speedup vs baseline: 2.6038x; 1.1736x over previous
#include <cuda_runtime.h>
#include <math.h>
#include <stdint.h>

// Problem constants
#define Bsz 8
#define SEQ 1024
#define EMB 1024
#define NH  16
#define HS  64
#define M_TOT (Bsz * SEQ)   // 8192

// Scratch. NOTE: g_xr, g_wt, g_wpr, g_att are stored with columns permuted
// within each 8-group: orig col c -> pos (c<4 ? 2c : 2(c-4)+1), so that MMA
// fragment k-pairs (c4, c4+4) are adjacent in smem (ld.shared.v2).
__device__ float g_q[Bsz * NH * SEQ * HS];
__device__ float g_k[Bsz * NH * SEQ * HS];
__device__ float g_v[Bsz * NH * SEQ * HS];
__device__ float g_att[M_TOT * EMB];
__device__ float g_wt[3 * EMB * EMB];
__device__ float g_xr[M_TOT * EMB];
__device__ float g_wpr[EMB * EMB];

// ---------------------------------------------------------------------------
// Helpers
// ---------------------------------------------------------------------------
__device__ __forceinline__ uint32_t smem_u32(const void* p) {
    uint32_t a;
    asm("{ .reg .u64 t; cvta.to.shared.u64 t, %1; cvt.u32.u64 %0, t; }" : "=r"(a) : "l"(p));
    return a;
}
__device__ __forceinline__ float tf32_rna(float x) {
    uint32_t u;
    asm("cvt.rna.tf32.f32 %0, %1;" : "=r"(u) : "f"(x));
    return __uint_as_float(u);
}
#define CP_ASYNC16(dst, src) \
    asm volatile("cp.async.cg.shared.global [%0], [%1], 16;" :: "r"(dst), "l"(src))
#define CP_COMMIT() asm volatile("cp.async.commit_group;" ::: "memory")
#define CP_WAIT(n)  asm volatile("cp.async.wait_group %0;" :: "n"(n) : "memory")

__device__ __forceinline__ void mma_tf32(float* d, const uint32_t* a, const uint32_t* b) {
    asm volatile(
        "mma.sync.aligned.m16n8k8.row.col.f32.tf32.tf32.f32 "
        "{%0,%1,%2,%3}, {%4,%5,%6,%7}, {%8,%9}, {%0,%1,%2,%3};"
        : "+f"(d[0]), "+f"(d[1]), "+f"(d[2]), "+f"(d[3])
        : "r"(a[0]), "r"(a[1]), "r"(a[2]), "r"(a[3]), "r"(b[0]), "r"(b[1]));
}

// ---------------------------------------------------------------------------
// Prep: tf32-round + permute columns within 8-groups.
// One thread per 8-col group; permuted group = [c0,c4,c1,c5,c2,c6,c3,c7].
// ---------------------------------------------------------------------------
__global__ __launch_bounds__(256)
void round_perm_kernel(const float* __restrict__ in, float* __restrict__ out) {
    size_t g = (size_t)blockIdx.x * 256 + threadIdx.x;
    size_t base = g * 8;
    float4 a = *(const float4*)&in[base];
    float4 b = *(const float4*)&in[base + 4];
    float4 o0 = make_float4(tf32_rna(a.x), tf32_rna(b.x), tf32_rna(a.y), tf32_rna(b.y));
    float4 o1 = make_float4(tf32_rna(a.z), tf32_rna(b.z), tf32_rna(a.w), tf32_rna(b.w));
    *(float4*)&out[base] = o0;
    *(float4*)&out[base + 4] = o1;
}

// Transpose QKV weights -> g_wt[mat][j=h*64+d][e], tf32-rounded, e-permuted.
__global__ __launch_bounds__(256)
void wt_transpose(const float* __restrict__ Wq,
                  const float* __restrict__ Wk,
                  const float* __restrict__ Wv) {
    __shared__ float t[64][65];
    const int tid = threadIdx.x;
    const int et = blockIdx.x;
    const int h  = blockIdx.y;
    const int mat = blockIdx.z;
    const float* W = (mat == 0) ? Wq : (mat == 1) ? Wk : Wv;
    const float* src = W + (size_t)h * (EMB * HS) + (size_t)(et * 64) * HS;
    float* out = g_wt + (size_t)mat * (EMB * EMB);

    for (int i = tid; i < 64 * 64; i += 256) {
        int e = i >> 6, d = i & 63;
        t[e][d] = src[(size_t)e * HS + d];
    }
    __syncthreads();
    for (int i = tid; i < 64 * 64; i += 256) {
        int d = i >> 6, e = i & 63;
        int r = e & 7;
        int ep = (e & ~7) + ((r & 4) ? 2 * (r & 3) + 1 : 2 * r);
        out[(size_t)(h * 64 + d) * EMB + et * 64 + ep] = tf32_rna(t[e][d]);
    }
}

// ---------------------------------------------------------------------------
// tf32 mma.sync GEMM core: C[128,128] = A @ B^T, permuted-k inputs, v2 LDS.
// 256 threads = 8 warps 2(m)x4(n); warp tile 64x32; K-chunk 32, 2-stage.
// ---------------------------------------------------------------------------
#define LDF 40
#define TILE_F (128 * LDF)
#define BUF_BYTES (2 * TILE_F * 4)       // A+B one stage = 40960
#define MMA_SMEM_BYTES (2 * BUF_BYTES)   // 81920
#define NCHUNK (EMB / 32)

__device__ __forceinline__ void gemm_load_chunk(uint32_t base, int buf, int kc,
                                                const float* __restrict__ Ag,
                                                const float* __restrict__ Bg,
                                                int m0, int n0, int tid) {
    uint32_t a_s = base + (uint32_t)buf * BUF_BYTES;
    uint32_t b_s = a_s + TILE_F * 4;
    const float* ap = Ag + (size_t)m0 * EMB + kc * 32;
    const float* bp = Bg + (size_t)n0 * EMB + kc * 32;
#pragma unroll
    for (int i = 0; i < 4; ++i) {
        int idx = i * 256 + tid;
        int row = idx >> 3, c = idx & 7;
        CP_ASYNC16(a_s + row * (LDF * 4) + c * 16, ap + (size_t)row * EMB + c * 4);
    }
#pragma unroll
    for (int i = 0; i < 4; ++i) {
        int idx = i * 256 + tid;
        int row = idx >> 3, c = idx & 7;
        CP_ASYNC16(b_s + row * (LDF * 4) + c * 16, bp + (size_t)row * EMB + c * 4);
    }
    CP_COMMIT();
}

__device__ __forceinline__ void gemm_mainloop(char* smraw, uint32_t base,
                                              const float* __restrict__ Ag,
                                              const float* __restrict__ Bg,
                                              int m0, int n0,
                                              float acc[4][4][4]) {
    const int tid = threadIdx.x;
    const int wid = tid >> 5, lane = tid & 31;
    const int wm = wid & 1, wn = wid >> 1;
    const int r4 = lane >> 2, c4 = lane & 3;

    gemm_load_chunk(base, 0, 0, Ag, Bg, m0, n0, tid);
    gemm_load_chunk(base, 1, 1, Ag, Bg, m0, n0, tid);

    for (int kc = 0; kc < NCHUNK; ++kc) {
        if (kc + 1 < NCHUNK) { CP_WAIT(1); } else { CP_WAIT(0); }
        __syncthreads();

        const int buf = kc & 1;
        const float* As = (const float*)(smraw + (size_t)buf * BUF_BYTES);
        const float* Bs = As + TILE_F;

#pragma unroll
        for (int ks = 0; ks < 4; ++ks) {
            const int k0 = ks * 8;
            uint32_t af[4][4], bf[4][2];
#pragma unroll
            for (int mt = 0; mt < 4; ++mt) {
                int rb = (wm * 64 + mt * 16 + r4) * LDF + k0 + 2 * c4;
                float2 u = *(const float2*)&As[rb];            // (c4, c4+4) row r4
                float2 w = *(const float2*)&As[rb + 8 * LDF];  // row r4+8
                af[mt][0] = __float_as_uint(u.x);
                af[mt][1] = __float_as_uint(w.x);
                af[mt][2] = __float_as_uint(u.y);
                af[mt][3] = __float_as_uint(w.y);
            }
#pragma unroll
            for (int nt = 0; nt < 4; ++nt) {
                int nb = (wn * 32 + nt * 8 + r4) * LDF + k0 + 2 * c4;
                float2 u = *(const float2*)&Bs[nb];
                bf[nt][0] = __float_as_uint(u.x);
                bf[nt][1] = __float_as_uint(u.y);
            }
#pragma unroll
            for (int mt = 0; mt < 4; ++mt)
#pragma unroll
                for (int nt = 0; nt < 4; ++nt)
                    mma_tf32(acc[mt][nt], af[mt], bf[nt]);
        }
        __syncthreads();
        if (kc + 2 < NCHUNK)
            gemm_load_chunk(base, buf, kc + 2, Ag, Bg, m0, n0, tid);
    }
}

__global__ __launch_bounds__(256)
void qkv_mma(void) {
    extern __shared__ char sm[];
    uint32_t base = smem_u32(sm);
    const int tid = threadIdx.x;
    const int wid = tid >> 5, lane = tid & 31;
    const int wm = wid & 1, wn = wid >> 1;
    const int r4 = lane >> 2, c4 = lane & 3;
    const int mat = blockIdx.x >> 3;
    const int n0 = (blockIdx.x & 7) * 128;
    const int m0 = blockIdx.y * 128;
    float* out = (mat == 0) ? g_q : (mat == 1) ? g_k : g_v;
    const float* Bg = g_wt + (size_t)mat * (EMB * EMB);

    float acc[4][4][4] = {};
    gemm_mainloop(sm, base, g_xr, Bg, m0, n0, acc);

#pragma unroll
    for (int mt = 0; mt < 4; ++mt) {
#pragma unroll
        for (int nt = 0; nt < 4; ++nt) {
            int n = n0 + wn * 32 + nt * 8 + c4 * 2;
            int h_ = n >> 6, d_ = n & 63;
#pragma unroll
            for (int rr = 0; rr < 2; ++rr) {
                int m = m0 + wm * 64 + mt * 16 + r4 + rr * 8;
                int b_ = m >> 10, s_ = m & 1023;
                float2 v = make_float2(acc[mt][nt][rr * 2], acc[mt][nt][rr * 2 + 1]);
                *(float2*)&out[(((size_t)b_ * NH + h_) * SEQ + s_) * HS + d_] = v;
            }
        }
    }
}

__global__ __launch_bounds__(256)
void proj_mma(const float* __restrict__ bias, float* __restrict__ out) {
    extern __shared__ char sm[];
    uint32_t base = smem_u32(sm);
    const int tid = threadIdx.x;
    const int wid = tid >> 5, lane = tid & 31;
    const int wm = wid & 1, wn = wid >> 1;
    const int r4 = lane >> 2, c4 = lane & 3;
    const int n0 = blockIdx.x * 128;
    const int m0 = blockIdx.y * 128;

    float acc[4][4][4] = {};
    gemm_mainloop(sm, base, g_att, g_wpr, m0, n0, acc);

#pragma unroll
    for (int mt = 0; mt < 4; ++mt) {
#pragma unroll
        for (int nt = 0; nt < 4; ++nt) {
            int n = n0 + wn * 32 + nt * 8 + c4 * 2;
            float2 bv = *(const float2*)&bias[n];
#pragma unroll
            for (int rr = 0; rr < 2; ++rr) {
                int m = m0 + wm * 64 + mt * 16 + r4 + rr * 8;
                float2 v = make_float2(acc[mt][nt][rr * 2] + bv.x,
                                       acc[mt][nt][rr * 2 + 1] + bv.y);
                *(float2*)&out[(size_t)m * EMB + n] = v;
            }
        }
    }
}

// ---------------------------------------------------------------------------
// Kernel 2: causal flash attention, tf32 mma.sync, v2.
//  - Q/K hi-lo interleaved in smem: X[row][2d]=hi, [2d+1]=lo -> v2 frag loads
//  - V stored untransposed [t][d], stride 72 -> conflict-free B-frag loads
//  - P kept in registers; S-accum -> A-fragment via quad shfl (no Ps smem)
// Grid (8 qtiles of 128 rows, 128 bh), 256 threads = 8 warps x 16 rows.
// ---------------------------------------------------------------------------
#define QLD 136
#define KLD 136
#define VLD 72
#define ATTN_SMEM_FLOATS (128 * QLD + 64 * KLD + 64 * VLD)
#define ATTN_SMEM_BYTES  (ATTN_SMEM_FLOATS * 4)   // 122880

__global__ __launch_bounds__(256)
void attn_mma() {
    extern __shared__ float sf[];
    float* Qi = sf;                  // [128][136] interleaved hi/lo
    float* Ki = Qi + 128 * QLD;      // [64][136]
    float* Vs = Ki + 64 * KLD;       // [64][72]

    const int tid = threadIdx.x;
    const int w = tid >> 5, lane = tid & 31;
    const int r4 = lane >> 2, c4 = lane & 3;
    const int qb = lane & ~3;        // quad base lane
    const int qt = blockIdx.x;
    const int bh = blockIdx.y;

    const float* qsrc = g_q + ((size_t)bh * SEQ + (size_t)qt * 128) * HS;
    const float* ksrc = g_k + (size_t)bh * SEQ * HS;
    const float* vsrc = g_v + (size_t)bh * SEQ * HS;

    // Load Q (128x64), fold scale, interleaved hi/lo.
    const float scale = 0.125f;
    for (int i = tid * 4; i < 128 * 64; i += 1024) {
        int row = i >> 6, col = i & 63;
        float4 qv = *(const float4*)&qsrc[i];
        float vals[4] = {qv.x * scale, qv.y * scale, qv.z * scale, qv.w * scale};
        float hi0 = tf32_rna(vals[0]), hi1 = tf32_rna(vals[1]);
        float hi2 = tf32_rna(vals[2]), hi3 = tf32_rna(vals[3]);
        float4 s0 = make_float4(hi0, tf32_rna(vals[0] - hi0), hi1, tf32_rna(vals[1] - hi1));
        float4 s1 = make_float4(hi2, tf32_rna(vals[2] - hi2), hi3, tf32_rna(vals[3] - hi3));
        *(float4*)&Qi[row * QLD + 2 * col] = s0;
        *(float4*)&Qi[row * QLD + 2 * col + 4] = s1;
    }

    float m0 = -1e30f, m1 = -1e30f, l0 = 0.0f, l1 = 0.0f;
    float o[8][4] = {};

    const int jmax = 2 * qt + 1;
    for (int jt = 0; jt <= jmax; ++jt) {
        __syncthreads();

        const float* kp = ksrc + (size_t)jt * 64 * 64;
        const float* vp = vsrc + (size_t)jt * 64 * 64;
        for (int i = tid * 4; i < 64 * 64; i += 1024) {
            int t = i >> 6, d = i & 63;
            float4 kv4 = *(const float4*)&kp[i];
            float hi0 = tf32_rna(kv4.x), hi1 = tf32_rna(kv4.y);
            float hi2 = tf32_rna(kv4.z), hi3 = tf32_rna(kv4.w);
            float4 s0 = make_float4(hi0, tf32_rna(kv4.x - hi0), hi1, tf32_rna(kv4.y - hi1));
            float4 s1 = make_float4(hi2, tf32_rna(kv4.z - hi2), hi3, tf32_rna(kv4.w - hi3));
            *(float4*)&Ki[t * KLD + 2 * d] = s0;
            *(float4*)&Ki[t * KLD + 2 * d + 4] = s1;
            // V untransposed, rna'd
            float4 vv = *(const float4*)&vp[i];
            float4 vr = make_float4(tf32_rna(vv.x), tf32_rna(vv.y),
                                    tf32_rna(vv.z), tf32_rna(vv.w));
            *(float4*)&Vs[t * VLD + d] = vr;
        }
        __syncthreads();

        // --- S = Q@K^T (double-tf32), warp rows w*16..w*16+15 ---
        float sacc[8][4] = {};
#pragma unroll
        for (int ks = 0; ks < 8; ++ks) {
            const int kp2 = 2 * (ks * 8 + c4);
            uint32_t ah[4], al[4];
            {
                int ra = (w * 16 + r4) * QLD + kp2;
                float2 q0 = *(const float2*)&Qi[ra];            // col c4: (hi,lo)
                float2 q2 = *(const float2*)&Qi[ra + 8];        // col c4+4
                float2 q1 = *(const float2*)&Qi[ra + 8 * QLD];
                float2 q3 = *(const float2*)&Qi[ra + 8 * QLD + 8];
                ah[0] = __float_as_uint(q0.x); al[0] = __float_as_uint(q0.y);
                ah[1] = __float_as_uint(q1.x); al[1] = __float_as_uint(q1.y);
                ah[2] = __float_as_uint(q2.x); al[2] = __float_as_uint(q2.y);
                ah[3] = __float_as_uint(q3.x); al[3] = __float_as_uint(q3.y);
            }
#pragma unroll
            for (int nt = 0; nt < 8; ++nt) {
                int rb = (nt * 8 + r4) * KLD + kp2;
                float2 b0 = *(const float2*)&Ki[rb];
                float2 b1 = *(const float2*)&Ki[rb + 8];
                uint32_t bh_[2] = {__float_as_uint(b0.x), __float_as_uint(b1.x)};
                uint32_t bl_[2] = {__float_as_uint(b0.y), __float_as_uint(b1.y)};
                mma_tf32(sacc[nt], ah, bh_);
                mma_tf32(sacc[nt], ah, bl_);
                mma_tf32(sacc[nt], al, bh_);
            }
        }

        // --- causal mask on diagonal tiles ---
        if (jt >= 2 * qt) {
            int rg0 = qt * 128 + w * 16 + r4;
#pragma unroll
            for (int nt = 0; nt < 8; ++nt) {
                int cg = jt * 64 + nt * 8 + c4 * 2;
                if (cg > rg0)         sacc[nt][0] = -1e30f;
                if (cg + 1 > rg0)     sacc[nt][1] = -1e30f;
                if (cg > rg0 + 8)     sacc[nt][2] = -1e30f;
                if (cg + 1 > rg0 + 8) sacc[nt][3] = -1e30f;
            }
        }

        // --- online softmax (register, quad shfl reductions) ---
        float mx0 = m0, mx1 = m1;
#pragma unroll
        for (int nt = 0; nt < 8; ++nt) {
            mx0 = fmaxf(mx0, fmaxf(sacc[nt][0], sacc[nt][1]));
            mx1 = fmaxf(mx1, fmaxf(sacc[nt][2], sacc[nt][3]));
        }
        mx0 = fmaxf(mx0, __shfl_xor_sync(0xFFFFFFFFu, mx0, 1));
        mx0 = fmaxf(mx0, __shfl_xor_sync(0xFFFFFFFFu, mx0, 2));
        mx1 = fmaxf(mx1, __shfl_xor_sync(0xFFFFFFFFu, mx1, 1));
        mx1 = fmaxf(mx1, __shfl_xor_sync(0xFFFFFFFFu, mx1, 2));
        float a0 = __expf(m0 - mx0);
        float a1 = __expf(m1 - mx1);
        m0 = mx0; m1 = mx1;

        float s0 = 0.0f, s1 = 0.0f;
#pragma unroll
        for (int nt = 0; nt < 8; ++nt) {
            float p00 = tf32_rna(__expf(sacc[nt][0] - mx0));
            float p01 = tf32_rna(__expf(sacc[nt][1] - mx0));
            float p10 = tf32_rna(__expf(sacc[nt][2] - mx1));
            float p11 = tf32_rna(__expf(sacc[nt][3] - mx1));
            s0 += p00 + p01;
            s1 += p10 + p11;
            sacc[nt][0] = p00; sacc[nt][1] = p01;
            sacc[nt][2] = p10; sacc[nt][3] = p11;
        }
        s0 += __shfl_xor_sync(0xFFFFFFFFu, s0, 1);
        s0 += __shfl_xor_sync(0xFFFFFFFFu, s0, 2);
        s1 += __shfl_xor_sync(0xFFFFFFFFu, s1, 1);
        s1 += __shfl_xor_sync(0xFFFFFFFFu, s1, 2);
        l0 = l0 * a0 + s0;
        l1 = l1 * a1 + s1;

        // rescale O
#pragma unroll
        for (int nt = 0; nt < 8; ++nt) {
            o[nt][0] *= a0; o[nt][1] *= a0;
            o[nt][2] *= a1; o[nt][3] *= a1;
        }

        // --- O += P @ V (P A-fragment built via quad shfl from sacc) ---
        const int sl0 = qb + (c4 >> 1);
        const bool oddc = (c4 & 1);
#pragma unroll
        for (int ks = 0; ks < 8; ++ks) {
            float e00 = __shfl_sync(0xFFFFFFFFu, sacc[ks][0], sl0);
            float e01 = __shfl_sync(0xFFFFFFFFu, sacc[ks][1], sl0);
            float e10 = __shfl_sync(0xFFFFFFFFu, sacc[ks][2], sl0);
            float e11 = __shfl_sync(0xFFFFFFFFu, sacc[ks][3], sl0);
            float e20 = __shfl_sync(0xFFFFFFFFu, sacc[ks][0], sl0 + 2);
            float e21 = __shfl_sync(0xFFFFFFFFu, sacc[ks][1], sl0 + 2);
            float e30 = __shfl_sync(0xFFFFFFFFu, sacc[ks][2], sl0 + 2);
            float e31 = __shfl_sync(0xFFFFFFFFu, sacc[ks][3], sl0 + 2);
            uint32_t af[4];
            af[0] = __float_as_uint(oddc ? e01 : e00);  // (r4,    k=c4)
            af[1] = __float_as_uint(oddc ? e11 : e10);  // (r4+8,  k=c4)
            af[2] = __float_as_uint(oddc ? e21 : e20);  // (r4,    k=c4+4)
            af[3] = __float_as_uint(oddc ? e31 : e30);  // (r4+8,  k=c4+4)
            const int t0 = ks * 8 + c4;
#pragma unroll
            for (int nt = 0; nt < 8; ++nt) {
                uint32_t bf[2];
                bf[0] = __float_as_uint(Vs[t0 * VLD + nt * 8 + r4]);
                bf[1] = __float_as_uint(Vs[(t0 + 4) * VLD + nt * 8 + r4]);
                mma_tf32(o[nt], af, bf);
            }
        }
    }

    // Epilogue: normalize, tf32-round, write g_att [B,S,H,HS] with d permuted
    // within 8-groups (proj consumes permuted-k A).
    const int b_ = bh >> 4, h_ = bh & 15;
    const float inv0 = 1.0f / l0, inv1 = 1.0f / l1;
    const int row0 = qt * 128 + w * 16 + r4;
    float* o0base = &g_att[(((size_t)b_ * SEQ + row0) * NH + h_) * HS];
    float* o1base = &g_att[(((size_t)b_ * SEQ + row0 + 8) * NH + h_) * HS];
#pragma unroll
    for (int nt = 0; nt < 8; ++nt) {
        int d0 = nt * 8 + c4 * 2;
        int r0 = d0 & 7, r1 = r0 + 1;
        int p0 = (d0 & ~7) + ((r0 & 4) ? 2 * (r0 & 3) + 1 : 2 * r0);
        int p1 = (d0 & ~7) + ((r1 & 4) ? 2 * (r1 & 3) + 1 : 2 * r1);
        o0base[p0] = tf32_rna(o[nt][0] * inv0);
        o0base[p1] = tf32_rna(o[nt][1] * inv0);
        o1base[p0] = tf32_rna(o[nt][2] * inv1);
        o1base[p1] = tf32_rna(o[nt][3] * inv1);
    }
}

// ---------------------------------------------------------------------------
extern "C" void kernel_launch(void* const* d_in, const int* in_sizes, int n_in,
                              void* d_out, int out_size) {
    (void)in_sizes; (void)n_in; (void)out_size;
    const float* x     = (const float*)d_in[0];
    const float* Wq    = (const float*)d_in[1];
    const float* Wk    = (const float*)d_in[2];
    const float* Wv    = (const float*)d_in[3];
    const float* Wproj = (const float*)d_in[4];
    const float* bproj = (const float*)d_in[5];
    float* out = (float*)d_out;

    cudaFuncSetAttribute(qkv_mma, cudaFuncAttributeMaxDynamicSharedMemorySize, MMA_SMEM_BYTES);
    cudaFuncSetAttribute(proj_mma, cudaFuncAttributeMaxDynamicSharedMemorySize, MMA_SMEM_BYTES);
    cudaFuncSetAttribute(attn_mma, cudaFuncAttributeMaxDynamicSharedMemorySize, ATTN_SMEM_BYTES);

    float* p_xr = nullptr;  cudaGetSymbolAddress((void**)&p_xr, g_xr);
    float* p_wpr = nullptr; cudaGetSymbolAddress((void**)&p_wpr, g_wpr);

    round_perm_kernel<<<M_TOT * EMB / 8 / 256, 256>>>(x, p_xr);
    round_perm_kernel<<<EMB * EMB / 8 / 256, 256>>>(Wproj, p_wpr);
    wt_transpose<<<dim3(16, 16, 3), 256>>>(Wq, Wk, Wv);
    qkv_mma<<<dim3(24, 64), 256, MMA_SMEM_BYTES>>>();
    attn_mma<<<dim3(8, Bsz * NH), 256, ATTN_SMEM_BYTES>>>();
    proj_mma<<<dim3(8, 64), 256, MMA_SMEM_BYTES>>>(bproj, out);
}

// round 6
// speedup vs baseline: 3.0802x; 1.1830x over previous
#include <cuda_runtime.h>
#include <math.h>
#include <stdint.h>

// Problem constants
#define Bsz 8
#define SEQ 1024
#define EMB 1024
#define NH  16
#define HS  64
#define M_TOT (Bsz * SEQ)   // 8192

// Scratch layouts:
//  g_q, g_k : [BH][S][128] hi/lo interleaved tf32 pairs (Q pre-scaled by 0.125)
//  g_v      : [BH][S][64]  tf32-rounded
//  g_att    : [B,S,H*HS] with cols permuted within 8-groups (for proj A-frags)
//  g_xr/g_wt/g_wpr : permuted-k tf32 GEMM operands
__device__ float g_q[Bsz * NH * SEQ * 128];
__device__ float g_k[Bsz * NH * SEQ * 128];
__device__ float g_v[Bsz * NH * SEQ * HS];
__device__ float g_att[M_TOT * EMB];
__device__ float g_wt[3 * EMB * EMB];
__device__ float g_xr[M_TOT * EMB];
__device__ float g_wpr[EMB * EMB];

// ---------------------------------------------------------------------------
// Helpers
// ---------------------------------------------------------------------------
__device__ __forceinline__ uint32_t smem_u32(const void* p) {
    uint32_t a;
    asm("{ .reg .u64 t; cvta.to.shared.u64 t, %1; cvt.u32.u64 %0, t; }" : "=r"(a) : "l"(p));
    return a;
}
__device__ __forceinline__ float tf32_rna(float x) {
    uint32_t u;
    asm("cvt.rna.tf32.f32 %0, %1;" : "=r"(u) : "f"(x));
    return __uint_as_float(u);
}
#define CP_ASYNC16(dst, src) \
    asm volatile("cp.async.cg.shared.global [%0], [%1], 16;" :: "r"(dst), "l"(src))
#define CP_COMMIT() asm volatile("cp.async.commit_group;" ::: "memory")
#define CP_WAIT(n)  asm volatile("cp.async.wait_group %0;" :: "n"(n) : "memory")

__device__ __forceinline__ void mma_tf32(float* d, const uint32_t* a, const uint32_t* b) {
    asm volatile(
        "mma.sync.aligned.m16n8k8.row.col.f32.tf32.tf32.f32 "
        "{%0,%1,%2,%3}, {%4,%5,%6,%7}, {%8,%9}, {%0,%1,%2,%3};"
        : "+f"(d[0]), "+f"(d[1]), "+f"(d[2]), "+f"(d[3])
        : "r"(a[0]), "r"(a[1]), "r"(a[2]), "r"(a[3]), "r"(b[0]), "r"(b[1]));
}

// ---------------------------------------------------------------------------
// Prep kernels
// ---------------------------------------------------------------------------
__global__ __launch_bounds__(256)
void round_perm_kernel(const float* __restrict__ in, float* __restrict__ out) {
    size_t g = (size_t)blockIdx.x * 256 + threadIdx.x;
    size_t base = g * 8;
    float4 a = *(const float4*)&in[base];
    float4 b = *(const float4*)&in[base + 4];
    float4 o0 = make_float4(tf32_rna(a.x), tf32_rna(b.x), tf32_rna(a.y), tf32_rna(b.y));
    float4 o1 = make_float4(tf32_rna(a.z), tf32_rna(b.z), tf32_rna(a.w), tf32_rna(b.w));
    *(float4*)&out[base] = o0;
    *(float4*)&out[base + 4] = o1;
}

__global__ __launch_bounds__(256)
void wt_transpose(const float* __restrict__ Wq,
                  const float* __restrict__ Wk,
                  const float* __restrict__ Wv) {
    __shared__ float t[64][65];
    const int tid = threadIdx.x;
    const int et = blockIdx.x;
    const int h  = blockIdx.y;
    const int mat = blockIdx.z;
    const float* W = (mat == 0) ? Wq : (mat == 1) ? Wk : Wv;
    const float* src = W + (size_t)h * (EMB * HS) + (size_t)(et * 64) * HS;
    float* out = g_wt + (size_t)mat * (EMB * EMB);

    for (int i = tid; i < 64 * 64; i += 256) {
        int e = i >> 6, d = i & 63;
        t[e][d] = src[(size_t)e * HS + d];
    }
    __syncthreads();
    for (int i = tid; i < 64 * 64; i += 256) {
        int d = i >> 6, e = i & 63;
        int r = e & 7;
        int ep = (e & ~7) + ((r & 4) ? 2 * (r & 3) + 1 : 2 * r);
        out[(size_t)(h * 64 + d) * EMB + et * 64 + ep] = tf32_rna(t[e][d]);
    }
}

// ---------------------------------------------------------------------------
// tf32 mma.sync GEMM core (as R5): C[128,128] = A @ B^T
// ---------------------------------------------------------------------------
#define LDF 40
#define TILE_F (128 * LDF)
#define BUF_BYTES (2 * TILE_F * 4)
#define MMA_SMEM_BYTES (2 * BUF_BYTES)
#define NCHUNK (EMB / 32)

__device__ __forceinline__ void gemm_load_chunk(uint32_t base, int buf, int kc,
                                                const float* __restrict__ Ag,
                                                const float* __restrict__ Bg,
                                                int m0, int n0, int tid) {
    uint32_t a_s = base + (uint32_t)buf * BUF_BYTES;
    uint32_t b_s = a_s + TILE_F * 4;
    const float* ap = Ag + (size_t)m0 * EMB + kc * 32;
    const float* bp = Bg + (size_t)n0 * EMB + kc * 32;
#pragma unroll
    for (int i = 0; i < 4; ++i) {
        int idx = i * 256 + tid;
        int row = idx >> 3, c = idx & 7;
        CP_ASYNC16(a_s + row * (LDF * 4) + c * 16, ap + (size_t)row * EMB + c * 4);
    }
#pragma unroll
    for (int i = 0; i < 4; ++i) {
        int idx = i * 256 + tid;
        int row = idx >> 3, c = idx & 7;
        CP_ASYNC16(b_s + row * (LDF * 4) + c * 16, bp + (size_t)row * EMB + c * 4);
    }
    CP_COMMIT();
}

__device__ __forceinline__ void gemm_mainloop(char* smraw, uint32_t base,
                                              const float* __restrict__ Ag,
                                              const float* __restrict__ Bg,
                                              int m0, int n0,
                                              float acc[4][4][4]) {
    const int tid = threadIdx.x;
    const int wid = tid >> 5, lane = tid & 31;
    const int wm = wid & 1, wn = wid >> 1;
    const int r4 = lane >> 2, c4 = lane & 3;

    gemm_load_chunk(base, 0, 0, Ag, Bg, m0, n0, tid);
    gemm_load_chunk(base, 1, 1, Ag, Bg, m0, n0, tid);

    for (int kc = 0; kc < NCHUNK; ++kc) {
        if (kc + 1 < NCHUNK) { CP_WAIT(1); } else { CP_WAIT(0); }
        __syncthreads();

        const int buf = kc & 1;
        const float* As = (const float*)(smraw + (size_t)buf * BUF_BYTES);
        const float* Bs = As + TILE_F;

#pragma unroll
        for (int ks = 0; ks < 4; ++ks) {
            const int k0 = ks * 8;
            uint32_t af[4][4], bf[4][2];
#pragma unroll
            for (int mt = 0; mt < 4; ++mt) {
                int rb = (wm * 64 + mt * 16 + r4) * LDF + k0 + 2 * c4;
                float2 u = *(const float2*)&As[rb];
                float2 w = *(const float2*)&As[rb + 8 * LDF];
                af[mt][0] = __float_as_uint(u.x);
                af[mt][1] = __float_as_uint(w.x);
                af[mt][2] = __float_as_uint(u.y);
                af[mt][3] = __float_as_uint(w.y);
            }
#pragma unroll
            for (int nt = 0; nt < 4; ++nt) {
                int nb = (wn * 32 + nt * 8 + r4) * LDF + k0 + 2 * c4;
                float2 u = *(const float2*)&Bs[nb];
                bf[nt][0] = __float_as_uint(u.x);
                bf[nt][1] = __float_as_uint(u.y);
            }
#pragma unroll
            for (int mt = 0; mt < 4; ++mt)
#pragma unroll
                for (int nt = 0; nt < 4; ++nt)
                    mma_tf32(acc[mt][nt], af[mt], bf[nt]);
        }
        __syncthreads();
        if (kc + 2 < NCHUNK)
            gemm_load_chunk(base, buf, kc + 2, Ag, Bg, m0, n0, tid);
    }
}

// ---------------------------------------------------------------------------
// Kernel 1: QKV projection; epilogue pre-formats Q/K (hi/lo interleave,
// Q pre-scaled) and V (rna) for the attention kernel.
// ---------------------------------------------------------------------------
__global__ __launch_bounds__(256)
void qkv_mma(void) {
    extern __shared__ char sm[];
    uint32_t base = smem_u32(sm);
    const int tid = threadIdx.x;
    const int wid = tid >> 5, lane = tid & 31;
    const int wm = wid & 1, wn = wid >> 1;
    const int r4 = lane >> 2, c4 = lane & 3;
    const int mat = blockIdx.x >> 3;
    const int n0 = (blockIdx.x & 7) * 128;
    const int m0 = blockIdx.y * 128;
    const float* Bg = g_wt + (size_t)mat * (EMB * EMB);

    float acc[4][4][4] = {};
    gemm_mainloop(sm, base, g_xr, Bg, m0, n0, acc);

    const float qscale = (mat == 0) ? 0.125f : 1.0f;
#pragma unroll
    for (int mt = 0; mt < 4; ++mt) {
#pragma unroll
        for (int nt = 0; nt < 4; ++nt) {
            int n = n0 + wn * 32 + nt * 8 + c4 * 2;
            int h_ = n >> 6, d_ = n & 63;
#pragma unroll
            for (int rr = 0; rr < 2; ++rr) {
                int m = m0 + wm * 64 + mt * 16 + r4 + rr * 8;
                int b_ = m >> 10, s_ = m & 1023;
                size_t bhs = ((size_t)(b_ * NH + h_) * SEQ + s_);
                float vx = acc[mt][nt][rr * 2];
                float vy = acc[mt][nt][rr * 2 + 1];
                if (mat == 2) {
                    float2 v = make_float2(tf32_rna(vx), tf32_rna(vy));
                    *(float2*)&g_v[bhs * HS + d_] = v;
                } else {
                    float x0 = vx * qscale, x1 = vy * qscale;
                    float h0 = tf32_rna(x0), h1 = tf32_rna(x1);
                    float4 v = make_float4(h0, tf32_rna(x0 - h0),
                                           h1, tf32_rna(x1 - h1));
                    float* dst = (mat == 0) ? g_q : g_k;
                    *(float4*)&dst[bhs * 128 + 2 * d_] = v;
                }
            }
        }
    }
}

// ---------------------------------------------------------------------------
// Kernel 3: output projection (unchanged).
// ---------------------------------------------------------------------------
__global__ __launch_bounds__(256)
void proj_mma(const float* __restrict__ bias, float* __restrict__ out) {
    extern __shared__ char sm[];
    uint32_t base = smem_u32(sm);
    const int tid = threadIdx.x;
    const int wid = tid >> 5, lane = tid & 31;
    const int wm = wid & 1, wn = wid >> 1;
    const int r4 = lane >> 2, c4 = lane & 3;
    const int n0 = blockIdx.x * 128;
    const int m0 = blockIdx.y * 128;

    float acc[4][4][4] = {};
    gemm_mainloop(sm, base, g_att, g_wpr, m0, n0, acc);

#pragma unroll
    for (int mt = 0; mt < 4; ++mt) {
#pragma unroll
        for (int nt = 0; nt < 4; ++nt) {
            int n = n0 + wn * 32 + nt * 8 + c4 * 2;
            float2 bv = *(const float2*)&bias[n];
#pragma unroll
            for (int rr = 0; rr < 2; ++rr) {
                int m = m0 + wm * 64 + mt * 16 + r4 + rr * 8;
                float2 v = make_float2(acc[mt][nt][rr * 2] + bv.x,
                                       acc[mt][nt][rr * 2 + 1] + bv.y);
                *(float2*)&out[(size_t)m * EMB + n] = v;
            }
        }
    }
}

// ---------------------------------------------------------------------------
// Kernel 2: causal flash attention, tf32 mma.sync, v3:
//  - all conversions pre-done; tiles are pure cp.async copies
//  - K/V double-buffered (load j+1 overlaps compute j)
//  - fully-masked warps skip compute on the last diagonal tile
// Grid (8, 128); qt = 7 - blockIdx.x (heavy blocks first). 256 thr = 8 warps.
// ---------------------------------------------------------------------------
#define QLD 136
#define KLD 136
#define VLD 72
#define ATTN_SMEM_FLOATS (128 * QLD + 2 * 64 * KLD + 2 * 64 * VLD)
#define ATTN_SMEM_BYTES  (ATTN_SMEM_FLOATS * 4)   // 176,128

__device__ __forceinline__ void attn_load_kv(uint32_t k_s, uint32_t v_s, int buf,
                                             const float* __restrict__ ksrc,
                                             const float* __restrict__ vsrc,
                                             int jt, int tid) {
    uint32_t kd = k_s + (uint32_t)buf * (64 * KLD * 4);
    uint32_t vd = v_s + (uint32_t)buf * (64 * VLD * 4);
    const float* kp = ksrc + (size_t)jt * 64 * 128;
    const float* vp = vsrc + (size_t)jt * 64 * 64;
#pragma unroll
    for (int i = 0; i < 8; ++i) {
        int idx = i * 256 + tid;          // 0..2047
        int row = idx >> 5, c = idx & 31;
        CP_ASYNC16(kd + (row * KLD + c * 4) * 4, kp + row * 128 + c * 4);
    }
#pragma unroll
    for (int i = 0; i < 4; ++i) {
        int idx = i * 256 + tid;          // 0..1023
        int row = idx >> 4, c = idx & 15;
        CP_ASYNC16(vd + (row * VLD + c * 4) * 4, vp + row * 64 + c * 4);
    }
    CP_COMMIT();
}

__global__ __launch_bounds__(256)
void attn_mma() {
    extern __shared__ float sf[];
    float* Qi = sf;                       // [128][136]
    float* Kb = Qi + 128 * QLD;           // 2 x [64][136]
    float* Vbf = Kb + 2 * 64 * KLD;       // 2 x [64][72]

    const int tid = threadIdx.x;
    const int w = tid >> 5, lane = tid & 31;
    const int r4 = lane >> 2, c4 = lane & 3;
    const int qb = lane & ~3;
    const int qt = 7 - blockIdx.x;
    const int bh = blockIdx.y;

    const float* qsrc = g_q + ((size_t)bh * SEQ + (size_t)qt * 128) * 128;
    const float* ksrc = g_k + (size_t)bh * SEQ * 128;
    const float* vsrc = g_v + (size_t)bh * SEQ * HS;

    uint32_t q_s = smem_u32(Qi);
    uint32_t k_s = smem_u32(Kb);
    uint32_t v_s = smem_u32(Vbf);

    // Q load (group 0)
#pragma unroll
    for (int i = 0; i < 16; ++i) {
        int idx = i * 256 + tid;          // 0..4095
        int row = idx >> 5, c = idx & 31;
        CP_ASYNC16(q_s + (row * QLD + c * 4) * 4, qsrc + row * 128 + c * 4);
    }
    CP_COMMIT();

    const int jmax = 2 * qt + 1;
    attn_load_kv(k_s, v_s, 0, ksrc, vsrc, 0, tid);
    attn_load_kv(k_s, v_s, 1, ksrc, vsrc, 1, tid);

    float m0 = -1e30f, m1 = -1e30f, l0 = 0.0f, l1 = 0.0f;
    float o[8][4] = {};

    for (int jt = 0; jt <= jmax; ++jt) {
        if (jt < jmax) { CP_WAIT(1); } else { CP_WAIT(0); }
        __syncthreads();

        const int buf = jt & 1;
        const float* Ki = Kb + buf * 64 * KLD;
        const float* Vs = Vbf + buf * 64 * VLD;

        // Fully-masked warp on last diagonal tile: nothing to do.
        const bool active = (jt * 64 <= qt * 128 + w * 16 + 15);
        if (active) {
            // --- S = Q@K^T (double-tf32) ---
            float sacc[8][4] = {};
#pragma unroll
            for (int ks = 0; ks < 8; ++ks) {
                const int kp2 = 2 * (ks * 8 + c4);
                uint32_t ah[4], al[4];
                {
                    int ra = (w * 16 + r4) * QLD + kp2;
                    float2 q0 = *(const float2*)&Qi[ra];
                    float2 q2 = *(const float2*)&Qi[ra + 8];
                    float2 q1 = *(const float2*)&Qi[ra + 8 * QLD];
                    float2 q3 = *(const float2*)&Qi[ra + 8 * QLD + 8];
                    ah[0] = __float_as_uint(q0.x); al[0] = __float_as_uint(q0.y);
                    ah[1] = __float_as_uint(q1.x); al[1] = __float_as_uint(q1.y);
                    ah[2] = __float_as_uint(q2.x); al[2] = __float_as_uint(q2.y);
                    ah[3] = __float_as_uint(q3.x); al[3] = __float_as_uint(q3.y);
                }
#pragma unroll
                for (int nt = 0; nt < 8; ++nt) {
                    int rb = (nt * 8 + r4) * KLD + kp2;
                    float2 b0 = *(const float2*)&Ki[rb];
                    float2 b1 = *(const float2*)&Ki[rb + 8];
                    uint32_t bh_[2] = {__float_as_uint(b0.x), __float_as_uint(b1.x)};
                    uint32_t bl_[2] = {__float_as_uint(b0.y), __float_as_uint(b1.y)};
                    mma_tf32(sacc[nt], ah, bh_);
                    mma_tf32(sacc[nt], ah, bl_);
                    mma_tf32(sacc[nt], al, bh_);
                }
            }

            // --- causal mask on diagonal tiles ---
            if (jt >= 2 * qt) {
                int rg0 = qt * 128 + w * 16 + r4;
#pragma unroll
                for (int nt = 0; nt < 8; ++nt) {
                    int cg = jt * 64 + nt * 8 + c4 * 2;
                    if (cg > rg0)         sacc[nt][0] = -1e30f;
                    if (cg + 1 > rg0)     sacc[nt][1] = -1e30f;
                    if (cg > rg0 + 8)     sacc[nt][2] = -1e30f;
                    if (cg + 1 > rg0 + 8) sacc[nt][3] = -1e30f;
                }
            }

            // --- online softmax ---
            float mx0 = m0, mx1 = m1;
#pragma unroll
            for (int nt = 0; nt < 8; ++nt) {
                mx0 = fmaxf(mx0, fmaxf(sacc[nt][0], sacc[nt][1]));
                mx1 = fmaxf(mx1, fmaxf(sacc[nt][2], sacc[nt][3]));
            }
            mx0 = fmaxf(mx0, __shfl_xor_sync(0xFFFFFFFFu, mx0, 1));
            mx0 = fmaxf(mx0, __shfl_xor_sync(0xFFFFFFFFu, mx0, 2));
            mx1 = fmaxf(mx1, __shfl_xor_sync(0xFFFFFFFFu, mx1, 1));
            mx1 = fmaxf(mx1, __shfl_xor_sync(0xFFFFFFFFu, mx1, 2));
            float a0 = __expf(m0 - mx0);
            float a1 = __expf(m1 - mx1);
            m0 = mx0; m1 = mx1;

            float s0 = 0.0f, s1 = 0.0f;
#pragma unroll
            for (int nt = 0; nt < 8; ++nt) {
                float p00 = tf32_rna(__expf(sacc[nt][0] - mx0));
                float p01 = tf32_rna(__expf(sacc[nt][1] - mx0));
                float p10 = tf32_rna(__expf(sacc[nt][2] - mx1));
                float p11 = tf32_rna(__expf(sacc[nt][3] - mx1));
                s0 += p00 + p01;
                s1 += p10 + p11;
                sacc[nt][0] = p00; sacc[nt][1] = p01;
                sacc[nt][2] = p10; sacc[nt][3] = p11;
            }
            s0 += __shfl_xor_sync(0xFFFFFFFFu, s0, 1);
            s0 += __shfl_xor_sync(0xFFFFFFFFu, s0, 2);
            s1 += __shfl_xor_sync(0xFFFFFFFFu, s1, 1);
            s1 += __shfl_xor_sync(0xFFFFFFFFu, s1, 2);
            l0 = l0 * a0 + s0;
            l1 = l1 * a1 + s1;

#pragma unroll
            for (int nt = 0; nt < 8; ++nt) {
                o[nt][0] *= a0; o[nt][1] *= a0;
                o[nt][2] *= a1; o[nt][3] *= a1;
            }

            // --- O += P @ V ---
            const int sl0 = qb + (c4 >> 1);
            const bool oddc = (c4 & 1);
#pragma unroll
            for (int ks = 0; ks < 8; ++ks) {
                float e00 = __shfl_sync(0xFFFFFFFFu, sacc[ks][0], sl0);
                float e01 = __shfl_sync(0xFFFFFFFFu, sacc[ks][1], sl0);
                float e10 = __shfl_sync(0xFFFFFFFFu, sacc[ks][2], sl0);
                float e11 = __shfl_sync(0xFFFFFFFFu, sacc[ks][3], sl0);
                float e20 = __shfl_sync(0xFFFFFFFFu, sacc[ks][0], sl0 + 2);
                float e21 = __shfl_sync(0xFFFFFFFFu, sacc[ks][1], sl0 + 2);
                float e30 = __shfl_sync(0xFFFFFFFFu, sacc[ks][2], sl0 + 2);
                float e31 = __shfl_sync(0xFFFFFFFFu, sacc[ks][3], sl0 + 2);
                uint32_t af[4];
                af[0] = __float_as_uint(oddc ? e01 : e00);
                af[1] = __float_as_uint(oddc ? e11 : e10);
                af[2] = __float_as_uint(oddc ? e21 : e20);
                af[3] = __float_as_uint(oddc ? e31 : e30);
                const int t0 = ks * 8 + c4;
#pragma unroll
                for (int nt = 0; nt < 8; ++nt) {
                    uint32_t bf[2];
                    bf[0] = __float_as_uint(Vs[t0 * VLD + nt * 8 + r4]);
                    bf[1] = __float_as_uint(Vs[(t0 + 4) * VLD + nt * 8 + r4]);
                    mma_tf32(o[nt], af, bf);
                }
            }
        }

        __syncthreads();
        if (jt + 2 <= jmax)
            attn_load_kv(k_s, v_s, buf, ksrc, vsrc, jt + 2, tid);
    }

    // Epilogue: normalize, tf32-round, write g_att permuted within 8-groups.
    const int b_ = bh >> 4, h_ = bh & 15;
    const float inv0 = 1.0f / l0, inv1 = 1.0f / l1;
    const int row0 = qt * 128 + w * 16 + r4;
    float* o0base = &g_att[(((size_t)b_ * SEQ + row0) * NH + h_) * HS];
    float* o1base = &g_att[(((size_t)b_ * SEQ + row0 + 8) * NH + h_) * HS];
#pragma unroll
    for (int nt = 0; nt < 8; ++nt) {
        int d0 = nt * 8 + c4 * 2;
        int r0 = d0 & 7, r1 = r0 + 1;
        int p0 = (d0 & ~7) + ((r0 & 4) ? 2 * (r0 & 3) + 1 : 2 * r0);
        int p1 = (d0 & ~7) + ((r1 & 4) ? 2 * (r1 & 3) + 1 : 2 * r1);
        o0base[p0] = tf32_rna(o[nt][0] * inv0);
        o0base[p1] = tf32_rna(o[nt][1] * inv0);
        o1base[p0] = tf32_rna(o[nt][2] * inv1);
        o1base[p1] = tf32_rna(o[nt][3] * inv1);
    }
}

// ---------------------------------------------------------------------------
extern "C" void kernel_launch(void* const* d_in, const int* in_sizes, int n_in,
                              void* d_out, int out_size) {
    (void)in_sizes; (void)n_in; (void)out_size;
    const float* x     = (const float*)d_in[0];
    const float* Wq    = (const float*)d_in[1];
    const float* Wk    = (const float*)d_in[2];
    const float* Wv    = (const float*)d_in[3];
    const float* Wproj = (const float*)d_in[4];
    const float* bproj = (const float*)d_in[5];
    float* out = (float*)d_out;

    cudaFuncSetAttribute(qkv_mma, cudaFuncAttributeMaxDynamicSharedMemorySize, MMA_SMEM_BYTES);
    cudaFuncSetAttribute(proj_mma, cudaFuncAttributeMaxDynamicSharedMemorySize, MMA_SMEM_BYTES);
    cudaFuncSetAttribute(attn_mma, cudaFuncAttributeMaxDynamicSharedMemorySize, ATTN_SMEM_BYTES);

    float* p_xr = nullptr;  cudaGetSymbolAddress((void**)&p_xr, g_xr);
    float* p_wpr = nullptr; cudaGetSymbolAddress((void**)&p_wpr, g_wpr);

    round_perm_kernel<<<M_TOT * EMB / 8 / 256, 256>>>(x, p_xr);
    round_perm_kernel<<<EMB * EMB / 8 / 256, 256>>>(Wproj, p_wpr);
    wt_transpose<<<dim3(16, 16, 3), 256>>>(Wq, Wk, Wv);
    qkv_mma<<<dim3(24, 64), 256, MMA_SMEM_BYTES>>>();
    attn_mma<<<dim3(8, Bsz * NH), 256, ATTN_SMEM_BYTES>>>();
    proj_mma<<<dim3(8, 64), 256, MMA_SMEM_BYTES>>>(bproj, out);
}

// round 8
// speedup vs baseline: 3.1417x; 1.0200x over previous
#include <cuda_runtime.h>
#include <math.h>
#include <stdint.h>

// Problem constants
#define Bsz 8
#define SEQ 1024
#define EMB 1024
#define NH  16
#define HS  64
#define M_TOT (Bsz * SEQ)   // 8192

// Scratch layouts:
//  g_q, g_k : [BH][S][128] hi/lo interleaved tf32 pairs (Q pre-scaled by 0.125)
//  g_v      : [BH][tile jt][d][t]  V transposed per 64-token tile (NO t-perm), rna'd
//  g_att    : [B,S,H*HS] cols permuted within 8-groups (proj A-frags)
//  g_xr/g_wt/g_wpr : permuted-k tf32 GEMM operands
__device__ float g_q[Bsz * NH * SEQ * 128];
__device__ float g_k[Bsz * NH * SEQ * 128];
__device__ float g_v[Bsz * NH * SEQ * HS];
__device__ float g_att[M_TOT * EMB];
__device__ float g_wt[3 * EMB * EMB];
__device__ float g_xr[M_TOT * EMB];
__device__ float g_wpr[EMB * EMB];

// ---------------------------------------------------------------------------
// Helpers
// ---------------------------------------------------------------------------
__device__ __forceinline__ uint32_t smem_u32(const void* p) {
    uint32_t a;
    asm("{ .reg .u64 t; cvta.to.shared.u64 t, %1; cvt.u32.u64 %0, t; }" : "=r"(a) : "l"(p));
    return a;
}
__device__ __forceinline__ float tf32_rna(float x) {
    uint32_t u;
    asm("cvt.rna.tf32.f32 %0, %1;" : "=r"(u) : "f"(x));
    return __uint_as_float(u);
}
__device__ __forceinline__ int perm8(int t) {   // pair-permute within 8-group
    int r = t & 7;
    return (t & ~7) + ((r & 4) ? 2 * (r & 3) + 1 : 2 * r);
}
#define CP_ASYNC16(dst, src) \
    asm volatile("cp.async.cg.shared.global [%0], [%1], 16;" :: "r"(dst), "l"(src))
#define CP_COMMIT() asm volatile("cp.async.commit_group;" ::: "memory")
#define CP_WAIT(n)  asm volatile("cp.async.wait_group %0;" :: "n"(n) : "memory")

__device__ __forceinline__ void mma_tf32(float* d, const uint32_t* a, const uint32_t* b) {
    asm volatile(
        "mma.sync.aligned.m16n8k8.row.col.f32.tf32.tf32.f32 "
        "{%0,%1,%2,%3}, {%4,%5,%6,%7}, {%8,%9}, {%0,%1,%2,%3};"
        : "+f"(d[0]), "+f"(d[1]), "+f"(d[2]), "+f"(d[3])
        : "r"(a[0]), "r"(a[1]), "r"(a[2]), "r"(a[3]), "r"(b[0]), "r"(b[1]));
}

// ---------------------------------------------------------------------------
// Prep kernels
// ---------------------------------------------------------------------------
__global__ __launch_bounds__(256)
void round_perm_kernel(const float* __restrict__ in, float* __restrict__ out) {
    size_t g = (size_t)blockIdx.x * 256 + threadIdx.x;
    size_t base = g * 8;
    float4 a = *(const float4*)&in[base];
    float4 b = *(const float4*)&in[base + 4];
    float4 o0 = make_float4(tf32_rna(a.x), tf32_rna(b.x), tf32_rna(a.y), tf32_rna(b.y));
    float4 o1 = make_float4(tf32_rna(a.z), tf32_rna(b.z), tf32_rna(a.w), tf32_rna(b.w));
    *(float4*)&out[base] = o0;
    *(float4*)&out[base + 4] = o1;
}

__global__ __launch_bounds__(256)
void wt_transpose(const float* __restrict__ Wq,
                  const float* __restrict__ Wk,
                  const float* __restrict__ Wv) {
    __shared__ float t[64][65];
    const int tid = threadIdx.x;
    const int et = blockIdx.x;
    const int h  = blockIdx.y;
    const int mat = blockIdx.z;
    const float* W = (mat == 0) ? Wq : (mat == 1) ? Wk : Wv;
    const float* src = W + (size_t)h * (EMB * HS) + (size_t)(et * 64) * HS;
    float* out = g_wt + (size_t)mat * (EMB * EMB);

    for (int i = tid; i < 64 * 64; i += 256) {
        int e = i >> 6, d = i & 63;
        t[e][d] = src[(size_t)e * HS + d];
    }
    __syncthreads();
    for (int i = tid; i < 64 * 64; i += 256) {
        int d = i >> 6, e = i & 63;
        out[(size_t)(h * 64 + d) * EMB + et * 64 + perm8(e)] = tf32_rna(t[e][d]);
    }
}

// ---------------------------------------------------------------------------
// tf32 mma.sync GEMM core: C[128,128] = A @ B^T
// ---------------------------------------------------------------------------
#define LDF 40
#define TILE_F (128 * LDF)
#define BUF_BYTES (2 * TILE_F * 4)
#define MMA_SMEM_BYTES (2 * BUF_BYTES)
#define NCHUNK (EMB / 32)

__device__ __forceinline__ void gemm_load_chunk(uint32_t base, int buf, int kc,
                                                const float* __restrict__ Ag,
                                                const float* __restrict__ Bg,
                                                int m0, int n0, int tid) {
    uint32_t a_s = base + (uint32_t)buf * BUF_BYTES;
    uint32_t b_s = a_s + TILE_F * 4;
    const float* ap = Ag + (size_t)m0 * EMB + kc * 32;
    const float* bp = Bg + (size_t)n0 * EMB + kc * 32;
#pragma unroll
    for (int i = 0; i < 4; ++i) {
        int idx = i * 256 + tid;
        int row = idx >> 3, c = idx & 7;
        CP_ASYNC16(a_s + row * (LDF * 4) + c * 16, ap + (size_t)row * EMB + c * 4);
    }
#pragma unroll
    for (int i = 0; i < 4; ++i) {
        int idx = i * 256 + tid;
        int row = idx >> 3, c = idx & 7;
        CP_ASYNC16(b_s + row * (LDF * 4) + c * 16, bp + (size_t)row * EMB + c * 4);
    }
    CP_COMMIT();
}

__device__ __forceinline__ void gemm_mainloop(char* smraw, uint32_t base,
                                              const float* __restrict__ Ag,
                                              const float* __restrict__ Bg,
                                              int m0, int n0,
                                              float acc[4][4][4]) {
    const int tid = threadIdx.x;
    const int wid = tid >> 5, lane = tid & 31;
    const int wm = wid & 1, wn = wid >> 1;
    const int r4 = lane >> 2, c4 = lane & 3;

    gemm_load_chunk(base, 0, 0, Ag, Bg, m0, n0, tid);
    gemm_load_chunk(base, 1, 1, Ag, Bg, m0, n0, tid);

    for (int kc = 0; kc < NCHUNK; ++kc) {
        if (kc + 1 < NCHUNK) { CP_WAIT(1); } else { CP_WAIT(0); }
        __syncthreads();

        const int buf = kc & 1;
        const float* As = (const float*)(smraw + (size_t)buf * BUF_BYTES);
        const float* Bs = As + TILE_F;

#pragma unroll
        for (int ks = 0; ks < 4; ++ks) {
            const int k0 = ks * 8;
            uint32_t af[4][4], bf[4][2];
#pragma unroll
            for (int mt = 0; mt < 4; ++mt) {
                int rb = (wm * 64 + mt * 16 + r4) * LDF + k0 + 2 * c4;
                float2 u = *(const float2*)&As[rb];
                float2 w = *(const float2*)&As[rb + 8 * LDF];
                af[mt][0] = __float_as_uint(u.x);
                af[mt][1] = __float_as_uint(w.x);
                af[mt][2] = __float_as_uint(u.y);
                af[mt][3] = __float_as_uint(w.y);
            }
#pragma unroll
            for (int nt = 0; nt < 4; ++nt) {
                int nb = (wn * 32 + nt * 8 + r4) * LDF + k0 + 2 * c4;
                float2 u = *(const float2*)&Bs[nb];
                bf[nt][0] = __float_as_uint(u.x);
                bf[nt][1] = __float_as_uint(u.y);
            }
#pragma unroll
            for (int mt = 0; mt < 4; ++mt)
#pragma unroll
                for (int nt = 0; nt < 4; ++nt)
                    mma_tf32(acc[mt][nt], af[mt], bf[nt]);
        }
        __syncthreads();
        if (kc + 2 < NCHUNK)
            gemm_load_chunk(base, buf, kc + 2, Ag, Bg, m0, n0, tid);
    }
}

// ---------------------------------------------------------------------------
// Kernel 1: QKV projection; epilogue formats Q/K hi/lo interleaved and V
// transposed-per-tile [bh][jt][d][t] (plain transpose), all rna'd.
// ---------------------------------------------------------------------------
__global__ __launch_bounds__(256)
void qkv_mma(void) {
    extern __shared__ char sm[];
    uint32_t base = smem_u32(sm);
    const int tid = threadIdx.x;
    const int wid = tid >> 5, lane = tid & 31;
    const int wm = wid & 1, wn = wid >> 1;
    const int r4 = lane >> 2, c4 = lane & 3;
    const int mat = blockIdx.x >> 3;
    const int n0 = (blockIdx.x & 7) * 128;
    const int m0 = blockIdx.y * 128;
    const float* Bg = g_wt + (size_t)mat * (EMB * EMB);

    float acc[4][4][4] = {};
    gemm_mainloop(sm, base, g_xr, Bg, m0, n0, acc);

    const float qscale = (mat == 0) ? 0.125f : 1.0f;
#pragma unroll
    for (int mt = 0; mt < 4; ++mt) {
#pragma unroll
        for (int nt = 0; nt < 4; ++nt) {
            int n = n0 + wn * 32 + nt * 8 + c4 * 2;
            int h_ = n >> 6, d_ = n & 63;
#pragma unroll
            for (int rr = 0; rr < 2; ++rr) {
                int m = m0 + wm * 64 + mt * 16 + r4 + rr * 8;
                int b_ = m >> 10, s_ = m & 1023;
                float vx = acc[mt][nt][rr * 2];
                float vy = acc[mt][nt][rr * 2 + 1];
                if (mat == 2) {
                    // V: [bh][tile][d][t]  (plain transpose, NO t-perm)
                    size_t tb = ((size_t)(b_ * NH + h_) * 16 + (s_ >> 6)) * 4096;
                    int t_ = s_ & 63;
                    g_v[tb + (size_t)d_ * 64 + t_] = tf32_rna(vx);
                    g_v[tb + (size_t)(d_ + 1) * 64 + t_] = tf32_rna(vy);
                } else {
                    size_t bhs = ((size_t)(b_ * NH + h_) * SEQ + s_);
                    float x0 = vx * qscale, x1 = vy * qscale;
                    float h0 = tf32_rna(x0), h1 = tf32_rna(x1);
                    float4 v = make_float4(h0, tf32_rna(x0 - h0),
                                           h1, tf32_rna(x1 - h1));
                    float* dst = (mat == 0) ? g_q : g_k;
                    *(float4*)&dst[bhs * 128 + 2 * d_] = v;
                }
            }
        }
    }
}

// ---------------------------------------------------------------------------
// Kernel 3: output projection (unchanged).
// ---------------------------------------------------------------------------
__global__ __launch_bounds__(256)
void proj_mma(const float* __restrict__ bias, float* __restrict__ out) {
    extern __shared__ char sm[];
    uint32_t base = smem_u32(sm);
    const int tid = threadIdx.x;
    const int wid = tid >> 5, lane = tid & 31;
    const int wm = wid & 1, wn = wid >> 1;
    const int r4 = lane >> 2, c4 = lane & 3;
    const int n0 = blockIdx.x * 128;
    const int m0 = blockIdx.y * 128;

    float acc[4][4][4] = {};
    gemm_mainloop(sm, base, g_att, g_wpr, m0, n0, acc);

#pragma unroll
    for (int mt = 0; mt < 4; ++mt) {
#pragma unroll
        for (int nt = 0; nt < 4; ++nt) {
            int n = n0 + wn * 32 + nt * 8 + c4 * 2;
            float2 bv = *(const float2*)&bias[n];
#pragma unroll
            for (int rr = 0; rr < 2; ++rr) {
                int m = m0 + wm * 64 + mt * 16 + r4 + rr * 8;
                float2 v = make_float2(acc[mt][nt][rr * 2] + bv.x,
                                       acc[mt][nt][rr * 2 + 1] + bv.y);
                *(float2*)&out[(size_t)m * EMB + n] = v;
            }
        }
    }
}

// ---------------------------------------------------------------------------
// Kernel 2: causal flash attention, tf32 mma.sync, v4 (fixed):
//  - O^T = V^T · P^T: S-accumulator doubles as the B-fragment. Its hw-k slots
//    (c4, c4+4) hold t = (2c4, 2c4+1), so the V^T A-fragment must source
//    t = (2c4, 2c4+1) too — i.e. a plain float2 load from UNPERMUTED V^T.
// Grid (8, 128); qt = 7 - blockIdx.x. 256 threads = 8 warps x 16 q-rows.
// ---------------------------------------------------------------------------
#define QLD 136
#define KLD 136
#define VLD 72
#define ATTN_SMEM_FLOATS (128 * QLD + 2 * 64 * KLD + 2 * 64 * VLD)
#define ATTN_SMEM_BYTES  (ATTN_SMEM_FLOATS * 4)   // 176,128

__device__ __forceinline__ void attn_load_kv(uint32_t k_s, uint32_t v_s, int buf,
                                             const float* __restrict__ ksrc,
                                             const float* __restrict__ vsrc,
                                             int jt, int tid) {
    uint32_t kd = k_s + (uint32_t)buf * (64 * KLD * 4);
    uint32_t vd = v_s + (uint32_t)buf * (64 * VLD * 4);
    const float* kp = ksrc + (size_t)jt * 64 * 128;
    const float* vp = vsrc + (size_t)jt * 64 * 64;   // rows = d, cols = t
#pragma unroll
    for (int i = 0; i < 8; ++i) {
        int idx = i * 256 + tid;
        int row = idx >> 5, c = idx & 31;
        CP_ASYNC16(kd + (row * KLD + c * 4) * 4, kp + row * 128 + c * 4);
    }
#pragma unroll
    for (int i = 0; i < 4; ++i) {
        int idx = i * 256 + tid;
        int row = idx >> 4, c = idx & 15;
        CP_ASYNC16(vd + (row * VLD + c * 4) * 4, vp + row * 64 + c * 4);
    }
    CP_COMMIT();
}

__global__ __launch_bounds__(256)
void attn_mma() {
    extern __shared__ float sf[];
    float* Qi = sf;                       // [128][136]
    float* Kb = Qi + 128 * QLD;           // 2 x [64][136]
    float* Vbf = Kb + 2 * 64 * KLD;       // 2 x [64][72]  (V^T)

    const int tid = threadIdx.x;
    const int w = tid >> 5, lane = tid & 31;
    const int r4 = lane >> 2, c4 = lane & 3;
    const int qt = 7 - blockIdx.x;
    const int bh = blockIdx.y;

    const float* qsrc = g_q + ((size_t)bh * SEQ + (size_t)qt * 128) * 128;
    const float* ksrc = g_k + (size_t)bh * SEQ * 128;
    const float* vsrc = g_v + (size_t)bh * SEQ * HS;

    uint32_t q_s = smem_u32(Qi);
    uint32_t k_s = smem_u32(Kb);
    uint32_t v_s = smem_u32(Vbf);

#pragma unroll
    for (int i = 0; i < 16; ++i) {
        int idx = i * 256 + tid;
        int row = idx >> 5, c = idx & 31;
        CP_ASYNC16(q_s + (row * QLD + c * 4) * 4, qsrc + row * 128 + c * 4);
    }
    CP_COMMIT();

    const int jmax = 2 * qt + 1;
    attn_load_kv(k_s, v_s, 0, ksrc, vsrc, 0, tid);
    attn_load_kv(k_s, v_s, 1, ksrc, vsrc, 1, tid);

    float m0 = -1e30f, m1 = -1e30f, l0 = 0.0f, l1 = 0.0f;
    // O^T accumulators: ot[db][qh]: regs = (d=db*16+r4(+8), q=qh*8+2c4(+1))
    float ot[4][2][4] = {};

    for (int jt = 0; jt <= jmax; ++jt) {
        if (jt < jmax) { CP_WAIT(1); } else { CP_WAIT(0); }
        __syncthreads();

        const int buf = jt & 1;
        const float* Ki = Kb + buf * 64 * KLD;
        const float* Vs = Vbf + buf * 64 * VLD;

        const bool active = (jt * 64 <= qt * 128 + w * 16 + 15);
        if (active) {
            // --- S = Q@K^T (double-tf32) ---
            float sacc[8][4] = {};
#pragma unroll
            for (int ks = 0; ks < 8; ++ks) {
                const int kp2 = 2 * (ks * 8 + c4);
                uint32_t ah[4], al[4];
                {
                    int ra = (w * 16 + r4) * QLD + kp2;
                    float2 q0 = *(const float2*)&Qi[ra];
                    float2 q2 = *(const float2*)&Qi[ra + 8];
                    float2 q1 = *(const float2*)&Qi[ra + 8 * QLD];
                    float2 q3 = *(const float2*)&Qi[ra + 8 * QLD + 8];
                    ah[0] = __float_as_uint(q0.x); al[0] = __float_as_uint(q0.y);
                    ah[1] = __float_as_uint(q1.x); al[1] = __float_as_uint(q1.y);
                    ah[2] = __float_as_uint(q2.x); al[2] = __float_as_uint(q2.y);
                    ah[3] = __float_as_uint(q3.x); al[3] = __float_as_uint(q3.y);
                }
#pragma unroll
                for (int nt = 0; nt < 8; ++nt) {
                    int rb = (nt * 8 + r4) * KLD + kp2;
                    float2 b0 = *(const float2*)&Ki[rb];
                    float2 b1 = *(const float2*)&Ki[rb + 8];
                    uint32_t bh_[2] = {__float_as_uint(b0.x), __float_as_uint(b1.x)};
                    uint32_t bl_[2] = {__float_as_uint(b0.y), __float_as_uint(b1.y)};
                    mma_tf32(sacc[nt], ah, bh_);
                    mma_tf32(sacc[nt], ah, bl_);
                    mma_tf32(sacc[nt], al, bh_);
                }
            }

            // --- causal mask on diagonal tiles ---
            if (jt >= 2 * qt) {
                int rg0 = qt * 128 + w * 16 + r4;
#pragma unroll
                for (int nt = 0; nt < 8; ++nt) {
                    int cg = jt * 64 + nt * 8 + c4 * 2;
                    if (cg > rg0)         sacc[nt][0] = -1e30f;
                    if (cg + 1 > rg0)     sacc[nt][1] = -1e30f;
                    if (cg > rg0 + 8)     sacc[nt][2] = -1e30f;
                    if (cg + 1 > rg0 + 8) sacc[nt][3] = -1e30f;
                }
            }

            // --- online softmax (rows r4, r4+8 of this warp) ---
            float mx0 = m0, mx1 = m1;
#pragma unroll
            for (int nt = 0; nt < 8; ++nt) {
                mx0 = fmaxf(mx0, fmaxf(sacc[nt][0], sacc[nt][1]));
                mx1 = fmaxf(mx1, fmaxf(sacc[nt][2], sacc[nt][3]));
            }
            mx0 = fmaxf(mx0, __shfl_xor_sync(0xFFFFFFFFu, mx0, 1));
            mx0 = fmaxf(mx0, __shfl_xor_sync(0xFFFFFFFFu, mx0, 2));
            mx1 = fmaxf(mx1, __shfl_xor_sync(0xFFFFFFFFu, mx1, 1));
            mx1 = fmaxf(mx1, __shfl_xor_sync(0xFFFFFFFFu, mx1, 2));
            float a0 = __expf(m0 - mx0);
            float a1 = __expf(m1 - mx1);
            m0 = mx0; m1 = mx1;

            float s0 = 0.0f, s1 = 0.0f;
#pragma unroll
            for (int nt = 0; nt < 8; ++nt) {
                float p00 = tf32_rna(__expf(sacc[nt][0] - mx0));
                float p01 = tf32_rna(__expf(sacc[nt][1] - mx0));
                float p10 = tf32_rna(__expf(sacc[nt][2] - mx1));
                float p11 = tf32_rna(__expf(sacc[nt][3] - mx1));
                s0 += p00 + p01;
                s1 += p10 + p11;
                sacc[nt][0] = p00; sacc[nt][1] = p01;
                sacc[nt][2] = p10; sacc[nt][3] = p11;
            }
            s0 += __shfl_xor_sync(0xFFFFFFFFu, s0, 1);
            s0 += __shfl_xor_sync(0xFFFFFFFFu, s0, 2);
            s1 += __shfl_xor_sync(0xFFFFFFFFu, s1, 1);
            s1 += __shfl_xor_sync(0xFFFFFFFFu, s1, 2);
            l0 = l0 * a0 + s0;
            l1 = l1 * a1 + s1;

            // Column rescale factors for O^T: a[q] for q = qh*8 + 2c4 (+1).
            float aq00 = __shfl_sync(0xFFFFFFFFu, a0, (2 * c4) * 4);
            float aq01 = __shfl_sync(0xFFFFFFFFu, a0, (2 * c4 + 1) * 4);
            float aq10 = __shfl_sync(0xFFFFFFFFu, a1, (2 * c4) * 4);
            float aq11 = __shfl_sync(0xFFFFFFFFu, a1, (2 * c4 + 1) * 4);
#pragma unroll
            for (int db = 0; db < 4; ++db) {
                ot[db][0][0] *= aq00; ot[db][0][1] *= aq01;
                ot[db][0][2] *= aq00; ot[db][0][3] *= aq01;
                ot[db][1][0] *= aq10; ot[db][1][1] *= aq11;
                ot[db][1][2] *= aq10; ot[db][1][3] *= aq11;
            }

            // --- O^T += V^T @ P^T : sacc IS the B-fragment ---
#pragma unroll
            for (int g = 0; g < 8; ++g) {
                uint32_t bf0[2] = {__float_as_uint(sacc[g][0]), __float_as_uint(sacc[g][1])};
                uint32_t bf1[2] = {__float_as_uint(sacc[g][2]), __float_as_uint(sacc[g][3])};
#pragma unroll
                for (int db = 0; db < 4; ++db) {
                    int ra = (db * 16 + r4) * VLD + g * 8 + 2 * c4;
                    float2 u = *(const float2*)&Vs[ra];          // t = 2c4, 2c4+1
                    float2 w2 = *(const float2*)&Vs[ra + 8 * VLD];
                    uint32_t af[4] = {__float_as_uint(u.x), __float_as_uint(w2.x),
                                      __float_as_uint(u.y), __float_as_uint(w2.y)};
                    mma_tf32(ot[db][0], af, bf0);
                    mma_tf32(ot[db][1], af, bf1);
                }
            }
        }

        __syncthreads();
        if (jt + 2 <= jmax)
            attn_load_kv(k_s, v_s, buf, ksrc, vsrc, jt + 2, tid);
    }

    // Epilogue: O = (O^T)^T / l, tf32-round, write g_att (cols 8-group-perm'd).
    const int b_ = bh >> 4, h_ = bh & 15;
    float lq00 = __shfl_sync(0xFFFFFFFFu, l0, (2 * c4) * 4);
    float lq01 = __shfl_sync(0xFFFFFFFFu, l0, (2 * c4 + 1) * 4);
    float lq10 = __shfl_sync(0xFFFFFFFFu, l1, (2 * c4) * 4);
    float lq11 = __shfl_sync(0xFFFFFFFFu, l1, (2 * c4 + 1) * 4);
    float iv[2][2] = {{1.0f / lq00, 1.0f / lq01}, {1.0f / lq10, 1.0f / lq11}};
    const int doff = (r4 & 4) ? 2 * (r4 & 3) + 1 : 2 * r4;   // perm8 offset of r4
#pragma unroll
    for (int db = 0; db < 4; ++db) {
        int p0 = db * 16 + doff;       // perm'd col of d = db*16 + r4
        int p8 = db * 16 + 8 + doff;   // perm'd col of d+8
#pragma unroll
        for (int qh = 0; qh < 2; ++qh) {
            int q0 = qt * 128 + w * 16 + qh * 8 + 2 * c4;
            size_t row0 = (((size_t)b_ * SEQ + q0) * NH + h_) * (size_t)HS;
            size_t row1 = (((size_t)b_ * SEQ + q0 + 1) * NH + h_) * (size_t)HS;
            g_att[row0 + p0] = tf32_rna(ot[db][qh][0] * iv[qh][0]);
            g_att[row1 + p0] = tf32_rna(ot[db][qh][1] * iv[qh][1]);
            g_att[row0 + p8] = tf32_rna(ot[db][qh][2] * iv[qh][0]);
            g_att[row1 + p8] = tf32_rna(ot[db][qh][3] * iv[qh][1]);
        }
    }
}

// ---------------------------------------------------------------------------
extern "C" void kernel_launch(void* const* d_in, const int* in_sizes, int n_in,
                              void* d_out, int out_size) {
    (void)in_sizes; (void)n_in; (void)out_size;
    const float* x     = (const float*)d_in[0];
    const float* Wq    = (const float*)d_in[1];
    const float* Wk    = (const float*)d_in[2];
    const float* Wv    = (const float*)d_in[3];
    const float* Wproj = (const float*)d_in[4];
    const float* bproj = (const float*)d_in[5];
    float* out = (float*)d_out;

    cudaFuncSetAttribute(qkv_mma, cudaFuncAttributeMaxDynamicSharedMemorySize, MMA_SMEM_BYTES);
    cudaFuncSetAttribute(proj_mma, cudaFuncAttributeMaxDynamicSharedMemorySize, MMA_SMEM_BYTES);
    cudaFuncSetAttribute(attn_mma, cudaFuncAttributeMaxDynamicSharedMemorySize, ATTN_SMEM_BYTES);

    float* p_xr = nullptr;  cudaGetSymbolAddress((void**)&p_xr, g_xr);
    float* p_wpr = nullptr; cudaGetSymbolAddress((void**)&p_wpr, g_wpr);

    round_perm_kernel<<<M_TOT * EMB / 8 / 256, 256>>>(x, p_xr);
    round_perm_kernel<<<EMB * EMB / 8 / 256, 256>>>(Wproj, p_wpr);
    wt_transpose<<<dim3(16, 16, 3), 256>>>(Wq, Wk, Wv);
    qkv_mma<<<dim3(24, 64), 256, MMA_SMEM_BYTES>>>();
    attn_mma<<<dim3(8, Bsz * NH), 256, ATTN_SMEM_BYTES>>>();
    proj_mma<<<dim3(8, 64), 256, MMA_SMEM_BYTES>>>(bproj, out);
}

// round 10
// speedup vs baseline: 3.7357x; 1.1891x over previous
#include <cuda_runtime.h>
#include <cuda_bf16.h>
#include <math.h>
#include <stdint.h>

// Problem constants
#define Bsz 8
#define SEQ 1024
#define EMB 1024
#define NH  16
#define HS  64
#define M_TOT (Bsz * SEQ)   // 8192

// Scratch layouts:
//  g_qu, g_ku : [BH][S][64 uint32] bf16 hi/lo pair-packed rows (Q pre-scaled):
//               per k16-block b (4 blocks), slot c (4): [h(p=8b+c), l, h(p=8b+c+4), l]
//               where pair p packs k-values (2p, 2p+1) as bf16x2 {lo=2p, hi=2p+1}.
//  g_v       : [BH][tile jt][d][t]  V transposed per 64-token tile, tf32-rna'd
//  g_att     : [B,S,H*HS] cols permuted within 8-groups (proj A-frags)
//  g_xr/g_wt/g_wpr : permuted-k tf32 GEMM operands
__device__ uint32_t g_qu[Bsz * NH * SEQ * 64];
__device__ uint32_t g_ku[Bsz * NH * SEQ * 64];
__device__ float g_v[Bsz * NH * SEQ * HS];
__device__ float g_att[M_TOT * EMB];
__device__ float g_wt[3 * EMB * EMB];
__device__ float g_xr[M_TOT * EMB];
__device__ float g_wpr[EMB * EMB];

// ---------------------------------------------------------------------------
// Helpers
// ---------------------------------------------------------------------------
__device__ __forceinline__ uint32_t smem_u32(const void* p) {
    uint32_t a;
    asm("{ .reg .u64 t; cvta.to.shared.u64 t, %1; cvt.u32.u64 %0, t; }" : "=r"(a) : "l"(p));
    return a;
}
__device__ __forceinline__ float tf32_rna(float x) {
    uint32_t u;
    asm("cvt.rna.tf32.f32 %0, %1;" : "=r"(u) : "f"(x));
    return __uint_as_float(u);
}
__device__ __forceinline__ int perm8(int t) {   // pair-permute within 8-group
    int r = t & 7;
    return (t & ~7) + ((r & 4) ? 2 * (r & 3) + 1 : 2 * r);
}
// Split (x,y) into bf16 hi/lo pairs: returns {hi_pack, lo_pack}, low half = x.
__device__ __forceinline__ uint2 bf16_split_pack(float x, float y) {
    __nv_bfloat16 hx = __float2bfloat16(x);
    __nv_bfloat16 hy = __float2bfloat16(y);
    float lx = x - __bfloat162float(hx);
    float ly = y - __bfloat162float(hy);
    __nv_bfloat162 hp = __halves2bfloat162(hx, hy);
    __nv_bfloat162 lp = __halves2bfloat162(__float2bfloat16(lx), __float2bfloat16(ly));
    uint2 r;
    r.x = *(uint32_t*)&hp;
    r.y = *(uint32_t*)&lp;
    return r;
}
#define CP_ASYNC16(dst, src) \
    asm volatile("cp.async.cg.shared.global [%0], [%1], 16;" :: "r"(dst), "l"(src))
#define CP_COMMIT() asm volatile("cp.async.commit_group;" ::: "memory")
#define CP_WAIT(n)  asm volatile("cp.async.wait_group %0;" :: "n"(n) : "memory")

__device__ __forceinline__ void mma_tf32(float* d, const uint32_t* a, const uint32_t* b) {
    asm volatile(
        "mma.sync.aligned.m16n8k8.row.col.f32.tf32.tf32.f32 "
        "{%0,%1,%2,%3}, {%4,%5,%6,%7}, {%8,%9}, {%0,%1,%2,%3};"
        : "+f"(d[0]), "+f"(d[1]), "+f"(d[2]), "+f"(d[3])
        : "r"(a[0]), "r"(a[1]), "r"(a[2]), "r"(a[3]), "r"(b[0]), "r"(b[1]));
}
__device__ __forceinline__ void mma_bf16(float* d, const uint32_t* a, const uint32_t* b) {
    asm volatile(
        "mma.sync.aligned.m16n8k16.row.col.f32.bf16.bf16.f32 "
        "{%0,%1,%2,%3}, {%4,%5,%6,%7}, {%8,%9}, {%0,%1,%2,%3};"
        : "+f"(d[0]), "+f"(d[1]), "+f"(d[2]), "+f"(d[3])
        : "r"(a[0]), "r"(a[1]), "r"(a[2]), "r"(a[3]), "r"(b[0]), "r"(b[1]));
}

// ---------------------------------------------------------------------------
// Prep kernels (unchanged)
// ---------------------------------------------------------------------------
__global__ __launch_bounds__(256)
void round_perm_kernel(const float* __restrict__ in, float* __restrict__ out) {
    size_t g = (size_t)blockIdx.x * 256 + threadIdx.x;
    size_t base = g * 8;
    float4 a = *(const float4*)&in[base];
    float4 b = *(const float4*)&in[base + 4];
    float4 o0 = make_float4(tf32_rna(a.x), tf32_rna(b.x), tf32_rna(a.y), tf32_rna(b.y));
    float4 o1 = make_float4(tf32_rna(a.z), tf32_rna(b.z), tf32_rna(a.w), tf32_rna(b.w));
    *(float4*)&out[base] = o0;
    *(float4*)&out[base + 4] = o1;
}

__global__ __launch_bounds__(256)
void wt_transpose(const float* __restrict__ Wq,
                  const float* __restrict__ Wk,
                  const float* __restrict__ Wv) {
    __shared__ float t[64][65];
    const int tid = threadIdx.x;
    const int et = blockIdx.x;
    const int h  = blockIdx.y;
    const int mat = blockIdx.z;
    const float* W = (mat == 0) ? Wq : (mat == 1) ? Wk : Wv;
    const float* src = W + (size_t)h * (EMB * HS) + (size_t)(et * 64) * HS;
    float* out = g_wt + (size_t)mat * (EMB * EMB);

    for (int i = tid; i < 64 * 64; i += 256) {
        int e = i >> 6, d = i & 63;
        t[e][d] = src[(size_t)e * HS + d];
    }
    __syncthreads();
    for (int i = tid; i < 64 * 64; i += 256) {
        int d = i >> 6, e = i & 63;
        out[(size_t)(h * 64 + d) * EMB + et * 64 + perm8(e)] = tf32_rna(t[e][d]);
    }
}

// ---------------------------------------------------------------------------
// tf32 mma.sync GEMM core (unchanged): C[128,128] = A @ B^T
// ---------------------------------------------------------------------------
#define LDF 40
#define TILE_F (128 * LDF)
#define BUF_BYTES (2 * TILE_F * 4)
#define MMA_SMEM_BYTES (2 * BUF_BYTES)
#define NCHUNK (EMB / 32)

__device__ __forceinline__ void gemm_load_chunk(uint32_t base, int buf, int kc,
                                                const float* __restrict__ Ag,
                                                const float* __restrict__ Bg,
                                                int m0, int n0, int tid) {
    uint32_t a_s = base + (uint32_t)buf * BUF_BYTES;
    uint32_t b_s = a_s + TILE_F * 4;
    const float* ap = Ag + (size_t)m0 * EMB + kc * 32;
    const float* bp = Bg + (size_t)n0 * EMB + kc * 32;
#pragma unroll
    for (int i = 0; i < 4; ++i) {
        int idx = i * 256 + tid;
        int row = idx >> 3, c = idx & 7;
        CP_ASYNC16(a_s + row * (LDF * 4) + c * 16, ap + (size_t)row * EMB + c * 4);
    }
#pragma unroll
    for (int i = 0; i < 4; ++i) {
        int idx = i * 256 + tid;
        int row = idx >> 3, c = idx & 7;
        CP_ASYNC16(b_s + row * (LDF * 4) + c * 16, bp + (size_t)row * EMB + c * 4);
    }
    CP_COMMIT();
}

__device__ __forceinline__ void gemm_mainloop(char* smraw, uint32_t base,
                                              const float* __restrict__ Ag,
                                              const float* __restrict__ Bg,
                                              int m0, int n0,
                                              float acc[4][4][4]) {
    const int tid = threadIdx.x;
    const int wid = tid >> 5, lane = tid & 31;
    const int wm = wid & 1, wn = wid >> 1;
    const int r4 = lane >> 2, c4 = lane & 3;

    gemm_load_chunk(base, 0, 0, Ag, Bg, m0, n0, tid);
    gemm_load_chunk(base, 1, 1, Ag, Bg, m0, n0, tid);

    for (int kc = 0; kc < NCHUNK; ++kc) {
        if (kc + 1 < NCHUNK) { CP_WAIT(1); } else { CP_WAIT(0); }
        __syncthreads();

        const int buf = kc & 1;
        const float* As = (const float*)(smraw + (size_t)buf * BUF_BYTES);
        const float* Bs = As + TILE_F;

#pragma unroll
        for (int ks = 0; ks < 4; ++ks) {
            const int k0 = ks * 8;
            uint32_t af[4][4], bf[4][2];
#pragma unroll
            for (int mt = 0; mt < 4; ++mt) {
                int rb = (wm * 64 + mt * 16 + r4) * LDF + k0 + 2 * c4;
                float2 u = *(const float2*)&As[rb];
                float2 w = *(const float2*)&As[rb + 8 * LDF];
                af[mt][0] = __float_as_uint(u.x);
                af[mt][1] = __float_as_uint(w.x);
                af[mt][2] = __float_as_uint(u.y);
                af[mt][3] = __float_as_uint(w.y);
            }
#pragma unroll
            for (int nt = 0; nt < 4; ++nt) {
                int nb = (wn * 32 + nt * 8 + r4) * LDF + k0 + 2 * c4;
                float2 u = *(const float2*)&Bs[nb];
                bf[nt][0] = __float_as_uint(u.x);
                bf[nt][1] = __float_as_uint(u.y);
            }
#pragma unroll
            for (int mt = 0; mt < 4; ++mt)
#pragma unroll
                for (int nt = 0; nt < 4; ++nt)
                    mma_tf32(acc[mt][nt], af[mt], bf[nt]);
        }
        __syncthreads();
        if (kc + 2 < NCHUNK)
            gemm_load_chunk(base, buf, kc + 2, Ag, Bg, m0, n0, tid);
    }
}

// ---------------------------------------------------------------------------
// Kernel 1: QKV projection; epilogue emits bf16 hi/lo packed Q/K rows and
// tf32 V transposed per tile.
// ---------------------------------------------------------------------------
__global__ __launch_bounds__(256)
void qkv_mma(void) {
    extern __shared__ char sm[];
    uint32_t base = smem_u32(sm);
    const int tid = threadIdx.x;
    const int wid = tid >> 5, lane = tid & 31;
    const int wm = wid & 1, wn = wid >> 1;
    const int r4 = lane >> 2, c4 = lane & 3;
    const int mat = blockIdx.x >> 3;
    const int n0 = (blockIdx.x & 7) * 128;
    const int m0 = blockIdx.y * 128;
    const float* Bg = g_wt + (size_t)mat * (EMB * EMB);

    float acc[4][4][4] = {};
    gemm_mainloop(sm, base, g_xr, Bg, m0, n0, acc);

    const float qscale = (mat == 0) ? 0.125f : 1.0f;
#pragma unroll
    for (int mt = 0; mt < 4; ++mt) {
#pragma unroll
        for (int nt = 0; nt < 4; ++nt) {
            int n = n0 + wn * 32 + nt * 8 + c4 * 2;
            int h_ = n >> 6, d_ = n & 63;
#pragma unroll
            for (int rr = 0; rr < 2; ++rr) {
                int m = m0 + wm * 64 + mt * 16 + r4 + rr * 8;
                int b_ = m >> 10, s_ = m & 1023;
                float vx = acc[mt][nt][rr * 2];
                float vy = acc[mt][nt][rr * 2 + 1];
                if (mat == 2) {
                    // V: [bh][tile][d][t]  tf32, plain transpose
                    size_t tb = ((size_t)(b_ * NH + h_) * 16 + (s_ >> 6)) * 4096;
                    int t_ = s_ & 63;
                    g_v[tb + (size_t)d_ * 64 + t_] = tf32_rna(vx);
                    g_v[tb + (size_t)(d_ + 1) * 64 + t_] = tf32_rna(vy);
                } else {
                    // Q/K: bf16 hi/lo pair-packed row of 64 uint32
                    size_t bhs = ((size_t)(b_ * NH + h_) * SEQ + s_);
                    uint2 pk = bf16_split_pack(vx * qscale, vy * qscale);
                    int p = d_ >> 1;
                    int b8 = p >> 3, pb = p & 7;
                    int u = b8 * 16 + (pb & 3) * 4 + ((pb >> 2) << 1);
                    uint32_t* dst = (mat == 0) ? g_qu : g_ku;
                    *(uint2*)&dst[bhs * 64 + u] = pk;
                }
            }
        }
    }
}

// ---------------------------------------------------------------------------
// Kernel 3: output projection (unchanged).
// ---------------------------------------------------------------------------
__global__ __launch_bounds__(256)
void proj_mma(const float* __restrict__ bias, float* __restrict__ out) {
    extern __shared__ char sm[];
    uint32_t base = smem_u32(sm);
    const int tid = threadIdx.x;
    const int wid = tid >> 5, lane = tid & 31;
    const int wm = wid & 1, wn = wid >> 1;
    const int r4 = lane >> 2, c4 = lane & 3;
    const int n0 = blockIdx.x * 128;
    const int m0 = blockIdx.y * 128;

    float acc[4][4][4] = {};
    gemm_mainloop(sm, base, g_att, g_wpr, m0, n0, acc);

#pragma unroll
    for (int mt = 0; mt < 4; ++mt) {
#pragma unroll
        for (int nt = 0; nt < 4; ++nt) {
            int n = n0 + wn * 32 + nt * 8 + c4 * 2;
            float2 bv = *(const float2*)&bias[n];
#pragma unroll
            for (int rr = 0; rr < 2; ++rr) {
                int m = m0 + wm * 64 + mt * 16 + r4 + rr * 8;
                float2 v = make_float2(acc[mt][nt][rr * 2] + bv.x,
                                       acc[mt][nt][rr * 2 + 1] + bv.y);
                *(float2*)&out[(size_t)m * EMB + n] = v;
            }
        }
    }
}

// ---------------------------------------------------------------------------
// Kernel 2: causal flash attention, v5 (load bounds FIXED):
//  - S = Q@K^T via double-bf16 (m16n8k16, 3-term hi/lo): 96 MMA/warp-tile
//  - PV via tf32 transposed trick (sacc as B-frag)
//  - 3-buffer K/V ring -> single __syncthreads per kv-tile
// Grid (8, 128); qt = 7 - blockIdx.x. 256 threads = 8 warps x 16 q-rows.
// ---------------------------------------------------------------------------
#define QLU 80            // Q/K smem row stride in uint32 (64 data + pad)
#define VLD 72
#define ATTN_SMEM_BYTES ((128 * QLU + 3 * 64 * QLU) * 4 + 3 * 64 * VLD * 4)  // 157,696

__device__ __forceinline__ void attn_load_kv(uint32_t k_s, uint32_t v_s, int buf,
                                             const uint32_t* __restrict__ ksrc,
                                             const float* __restrict__ vsrc,
                                             int jt, int tid) {
    uint32_t kd = k_s + (uint32_t)buf * (64 * QLU * 4);
    uint32_t vd = v_s + (uint32_t)buf * (64 * VLD * 4);
    const uint32_t* kp = ksrc + (size_t)jt * 64 * 64;
    const float* vp = vsrc + (size_t)jt * 64 * 64;
#pragma unroll
    for (int i = 0; i < 4; ++i) {         // K: 64 rows x 64 uint32 = 1024 x 16B
        int idx = i * 256 + tid;
        int row = idx >> 4, c = idx & 15;
        CP_ASYNC16(kd + (row * QLU + c * 4) * 4, kp + row * 64 + c * 4);
    }
#pragma unroll
    for (int i = 0; i < 4; ++i) {         // V: 64 rows x 64 f32 = 1024 x 16B
        int idx = i * 256 + tid;
        int row = idx >> 4, c = idx & 15;
        CP_ASYNC16(vd + (row * VLD + c * 4) * 4, vp + row * 64 + c * 4);
    }
    CP_COMMIT();
}

__global__ __launch_bounds__(256)
void attn_mma() {
    extern __shared__ uint32_t su[];
    uint32_t* Qi = su;                    // [128][80] uint32
    uint32_t* Kb = Qi + 128 * QLU;        // 3 x [64][80] uint32
    float* Vbf = (float*)(Kb + 3 * 64 * QLU);  // 3 x [64][72] f32

    const int tid = threadIdx.x;
    const int w = tid >> 5, lane = tid & 31;
    const int r4 = lane >> 2, c4 = lane & 3;
    const int qt = 7 - blockIdx.x;
    const int bh = blockIdx.y;

    const uint32_t* qsrc = g_qu + ((size_t)bh * SEQ + (size_t)qt * 128) * 64;
    const uint32_t* ksrc = g_ku + (size_t)bh * SEQ * 64;
    const float* vsrc = g_v + (size_t)bh * SEQ * HS;

    uint32_t q_s = smem_u32(Qi);
    uint32_t k_s = smem_u32(Kb);
    uint32_t v_s = smem_u32(Vbf);

    // Q load: 128 rows x 64 uint32 = 2048 x 16B
#pragma unroll
    for (int i = 0; i < 8; ++i) {
        int idx = i * 256 + tid;
        int row = idx >> 4, c = idx & 15;
        CP_ASYNC16(q_s + (row * QLU + c * 4) * 4, qsrc + row * 64 + c * 4);
    }
    CP_COMMIT();

    const int jmax = 2 * qt + 1;
    attn_load_kv(k_s, v_s, 0, ksrc, vsrc, 0, tid);
    attn_load_kv(k_s, v_s, 1, ksrc, vsrc, 1, tid);

    float m0 = -1e30f, m1 = -1e30f, l0 = 0.0f, l1 = 0.0f;
    float ot[4][2][4] = {};

    for (int jt = 0; jt <= jmax; ++jt) {
        if (jt + 1 <= jmax) { CP_WAIT(1); } else { CP_WAIT(0); }
        __syncthreads();
        if (jt + 2 <= jmax)   // safe: all warps passed jt-1 compute (prev sync)
            attn_load_kv(k_s, v_s, (jt + 2) % 3, ksrc, vsrc, jt + 2, tid);

        const int buf = jt % 3;
        const uint32_t* Ki = Kb + buf * 64 * QLU;
        const float* Vs = Vbf + buf * 64 * VLD;

        const bool active = (jt * 64 <= qt * 128 + w * 16 + 15);
        if (active) {
            // --- S = Q@K^T (double-bf16, 3-term) ---
            float sacc[8][4] = {};
#pragma unroll
            for (int kb = 0; kb < 4; ++kb) {
                int ra = (w * 16 + r4) * QLU + kb * 16 + c4 * 4;
                uint4 q0 = *(const uint4*)&Qi[ra];
                uint4 q1 = *(const uint4*)&Qi[ra + 8 * QLU];
                uint32_t Ah[4] = {q0.x, q1.x, q0.z, q1.z};
                uint32_t Al[4] = {q0.y, q1.y, q0.w, q1.w};
#pragma unroll
                for (int nt = 0; nt < 8; ++nt) {
                    uint4 kv = *(const uint4*)&Ki[(nt * 8 + r4) * QLU + kb * 16 + c4 * 4];
                    uint32_t Bh[2] = {kv.x, kv.z};
                    uint32_t Bl[2] = {kv.y, kv.w};
                    mma_bf16(sacc[nt], Ah, Bh);
                    mma_bf16(sacc[nt], Ah, Bl);
                    mma_bf16(sacc[nt], Al, Bh);
                }
            }

            // --- causal mask on diagonal tiles ---
            if (jt >= 2 * qt) {
                int rg0 = qt * 128 + w * 16 + r4;
#pragma unroll
                for (int nt = 0; nt < 8; ++nt) {
                    int cg = jt * 64 + nt * 8 + c4 * 2;
                    if (cg > rg0)         sacc[nt][0] = -1e30f;
                    if (cg + 1 > rg0)     sacc[nt][1] = -1e30f;
                    if (cg > rg0 + 8)     sacc[nt][2] = -1e30f;
                    if (cg + 1 > rg0 + 8) sacc[nt][3] = -1e30f;
                }
            }

            // --- online softmax ---
            float mx0 = m0, mx1 = m1;
#pragma unroll
            for (int nt = 0; nt < 8; ++nt) {
                mx0 = fmaxf(mx0, fmaxf(sacc[nt][0], sacc[nt][1]));
                mx1 = fmaxf(mx1, fmaxf(sacc[nt][2], sacc[nt][3]));
            }
            mx0 = fmaxf(mx0, __shfl_xor_sync(0xFFFFFFFFu, mx0, 1));
            mx0 = fmaxf(mx0, __shfl_xor_sync(0xFFFFFFFFu, mx0, 2));
            mx1 = fmaxf(mx1, __shfl_xor_sync(0xFFFFFFFFu, mx1, 1));
            mx1 = fmaxf(mx1, __shfl_xor_sync(0xFFFFFFFFu, mx1, 2));
            float a0 = __expf(m0 - mx0);
            float a1 = __expf(m1 - mx1);
            m0 = mx0; m1 = mx1;

            float s0 = 0.0f, s1 = 0.0f;
#pragma unroll
            for (int nt = 0; nt < 8; ++nt) {
                float p00 = tf32_rna(__expf(sacc[nt][0] - mx0));
                float p01 = tf32_rna(__expf(sacc[nt][1] - mx0));
                float p10 = tf32_rna(__expf(sacc[nt][2] - mx1));
                float p11 = tf32_rna(__expf(sacc[nt][3] - mx1));
                s0 += p00 + p01;
                s1 += p10 + p11;
                sacc[nt][0] = p00; sacc[nt][1] = p01;
                sacc[nt][2] = p10; sacc[nt][3] = p11;
            }
            s0 += __shfl_xor_sync(0xFFFFFFFFu, s0, 1);
            s0 += __shfl_xor_sync(0xFFFFFFFFu, s0, 2);
            s1 += __shfl_xor_sync(0xFFFFFFFFu, s1, 1);
            s1 += __shfl_xor_sync(0xFFFFFFFFu, s1, 2);
            l0 = l0 * a0 + s0;
            l1 = l1 * a1 + s1;

            // Column rescale factors for O^T
            float aq00 = __shfl_sync(0xFFFFFFFFu, a0, (2 * c4) * 4);
            float aq01 = __shfl_sync(0xFFFFFFFFu, a0, (2 * c4 + 1) * 4);
            float aq10 = __shfl_sync(0xFFFFFFFFu, a1, (2 * c4) * 4);
            float aq11 = __shfl_sync(0xFFFFFFFFu, a1, (2 * c4 + 1) * 4);
#pragma unroll
            for (int db = 0; db < 4; ++db) {
                ot[db][0][0] *= aq00; ot[db][0][1] *= aq01;
                ot[db][0][2] *= aq00; ot[db][0][3] *= aq01;
                ot[db][1][0] *= aq10; ot[db][1][1] *= aq11;
                ot[db][1][2] *= aq10; ot[db][1][3] *= aq11;
            }

            // --- O^T += V^T @ P^T (tf32; sacc IS the B-fragment) ---
#pragma unroll
            for (int g = 0; g < 8; ++g) {
                uint32_t bf0[2] = {__float_as_uint(sacc[g][0]), __float_as_uint(sacc[g][1])};
                uint32_t bf1[2] = {__float_as_uint(sacc[g][2]), __float_as_uint(sacc[g][3])};
#pragma unroll
                for (int db = 0; db < 4; ++db) {
                    int ra = (db * 16 + r4) * VLD + g * 8 + 2 * c4;
                    float2 u = *(const float2*)&Vs[ra];
                    float2 w2 = *(const float2*)&Vs[ra + 8 * VLD];
                    uint32_t af[4] = {__float_as_uint(u.x), __float_as_uint(w2.x),
                                      __float_as_uint(u.y), __float_as_uint(w2.y)};
                    mma_tf32(ot[db][0], af, bf0);
                    mma_tf32(ot[db][1], af, bf1);
                }
            }
        }
    }

    // Epilogue: O = (O^T)^T / l, tf32-round, write g_att (cols 8-group-perm'd).
    const int b_ = bh >> 4, h_ = bh & 15;
    float lq00 = __shfl_sync(0xFFFFFFFFu, l0, (2 * c4) * 4);
    float lq01 = __shfl_sync(0xFFFFFFFFu, l0, (2 * c4 + 1) * 4);
    float lq10 = __shfl_sync(0xFFFFFFFFu, l1, (2 * c4) * 4);
    float lq11 = __shfl_sync(0xFFFFFFFFu, l1, (2 * c4 + 1) * 4);
    float iv[2][2] = {{1.0f / lq00, 1.0f / lq01}, {1.0f / lq10, 1.0f / lq11}};
    const int doff = (r4 & 4) ? 2 * (r4 & 3) + 1 : 2 * r4;
#pragma unroll
    for (int db = 0; db < 4; ++db) {
        int p0 = db * 16 + doff;
        int p8 = db * 16 + 8 + doff;
#pragma unroll
        for (int qh = 0; qh < 2; ++qh) {
            int q0 = qt * 128 + w * 16 + qh * 8 + 2 * c4;
            size_t row0 = (((size_t)b_ * SEQ + q0) * NH + h_) * (size_t)HS;
            size_t row1 = (((size_t)b_ * SEQ + q0 + 1) * NH + h_) * (size_t)HS;
            g_att[row0 + p0] = tf32_rna(ot[db][qh][0] * iv[qh][0]);
            g_att[row1 + p0] = tf32_rna(ot[db][qh][1] * iv[qh][1]);
            g_att[row0 + p8] = tf32_rna(ot[db][qh][2] * iv[qh][0]);
            g_att[row1 + p8] = tf32_rna(ot[db][qh][3] * iv[qh][1]);
        }
    }
}

// ---------------------------------------------------------------------------
extern "C" void kernel_launch(void* const* d_in, const int* in_sizes, int n_in,
                              void* d_out, int out_size) {
    (void)in_sizes; (void)n_in; (void)out_size;
    const float* x     = (const float*)d_in[0];
    const float* Wq    = (const float*)d_in[1];
    const float* Wk    = (const float*)d_in[2];
    const float* Wv    = (const float*)d_in[3];
    const float* Wproj = (const float*)d_in[4];
    const float* bproj = (const float*)d_in[5];
    float* out = (float*)d_out;

    cudaFuncSetAttribute(qkv_mma, cudaFuncAttributeMaxDynamicSharedMemorySize, MMA_SMEM_BYTES);
    cudaFuncSetAttribute(proj_mma, cudaFuncAttributeMaxDynamicSharedMemorySize, MMA_SMEM_BYTES);
    cudaFuncSetAttribute(attn_mma, cudaFuncAttributeMaxDynamicSharedMemorySize, ATTN_SMEM_BYTES);

    float* p_xr = nullptr;  cudaGetSymbolAddress((void**)&p_xr, g_xr);
    float* p_wpr = nullptr; cudaGetSymbolAddress((void**)&p_wpr, g_wpr);

    round_perm_kernel<<<M_TOT * EMB / 8 / 256, 256>>>(x, p_xr);
    round_perm_kernel<<<EMB * EMB / 8 / 256, 256>>>(Wproj, p_wpr);
    wt_transpose<<<dim3(16, 16, 3), 256>>>(Wq, Wk, Wv);
    qkv_mma<<<dim3(24, 64), 256, MMA_SMEM_BYTES>>>();
    attn_mma<<<dim3(8, Bsz * NH), 256, ATTN_SMEM_BYTES>>>();
    proj_mma<<<dim3(8, 64), 256, MMA_SMEM_BYTES>>>(bproj, out);
}